// round 1
// baseline (speedup 1.0000x reference)
#include <cuda_runtime.h>
#include <math.h>

#define D_MODEL 1024
#define SEQ     2048
#define BATCH   2
#define NTOK    4096   // BATCH*SEQ
#define NHEAD   16
#define HD      64

// ---------------- scratch (no allocations allowed) ----------------
__device__ float g_ln1 [NTOK * D_MODEL];
__device__ float g_qkv [NTOK * 3 * D_MODEL];
__device__ float g_attn[NTOK * D_MODEL];
__device__ float g_x1  [NTOK * D_MODEL];
__device__ float g_ln2 [NTOK * D_MODEL];
__device__ float g_h   [NTOK * 4 * D_MODEL];

// ---------------- LayerNorm (torch-style: Bessel std, eps on std) ----------------
__global__ __launch_bounds__(256) void ln_kernel(const float* __restrict__ x,
                                                 const float* __restrict__ w,
                                                 const float* __restrict__ b,
                                                 float* __restrict__ y)
{
    int row = blockIdx.x;
    int tid = threadIdx.x;
    const float4* xr = (const float4*)(x + (size_t)row * D_MODEL);
    float4 v = xr[tid];                       // 256 threads * 4 = 1024

    __shared__ float red[8];

    float s = v.x + v.y + v.z + v.w;
    #pragma unroll
    for (int o = 16; o > 0; o >>= 1) s += __shfl_xor_sync(0xffffffffu, s, o);
    if ((tid & 31) == 0) red[tid >> 5] = s;
    __syncthreads();
    float tot = red[0] + red[1] + red[2] + red[3] + red[4] + red[5] + red[6] + red[7];
    float mean = tot * (1.0f / 1024.0f);

    float a0 = v.x - mean, a1 = v.y - mean, a2 = v.z - mean, a3 = v.w - mean;
    __syncthreads();   // red reuse
    float q = a0*a0 + a1*a1 + a2*a2 + a3*a3;
    #pragma unroll
    for (int o = 16; o > 0; o >>= 1) q += __shfl_xor_sync(0xffffffffu, q, o);
    if ((tid & 31) == 0) red[tid >> 5] = q;
    __syncthreads();
    float ssq = red[0] + red[1] + red[2] + red[3] + red[4] + red[5] + red[6] + red[7];

    float sd  = sqrtf(ssq * (1.0f / 1023.0f));   // ddof=1
    float inv = 1.0f / (sd + 1e-5f);             // eps added to std

    float4 wv = ((const float4*)w)[tid];
    float4 bv = ((const float4*)b)[tid];
    float4 o;
    o.x = wv.x * (a0 * inv) + bv.x;
    o.y = wv.y * (a1 * inv) + bv.y;
    o.z = wv.z * (a2 * inv) + bv.z;
    o.w = wv.w * (a3 * inv) + bv.w;
    ((float4*)(y + (size_t)row * D_MODEL))[tid] = o;
}

// ---------------- GELU (tanh approx) ----------------
__device__ __forceinline__ float gelu_f(float x)
{
    float x3 = x * x * x;
    return 0.5f * x * (1.0f + tanhf(0.7978845608028654f * (x + 0.044715f * x3)));
}

// ---------------- 128x128x8 fp32 GEMM, fused epilogues ----------------
// MODE 0: C = A@B + bias
// MODE 1: C = res + A@B + bias
// MODE 2: C = gelu(A@B + bias)
template<int MODE>
__global__ __launch_bounds__(256) void gemm_kernel(const float* __restrict__ A,
                                                   const float* __restrict__ Bm,
                                                   const float* __restrict__ bias,
                                                   const float* __restrict__ res,
                                                   float* __restrict__ C,
                                                   int M, int N, int K)
{
    __shared__ float As[8][128];
    __shared__ float Bs[8][128];

    int tid = threadIdx.x;
    int bx = blockIdx.x, by = blockIdx.y;
    int tx = tid & 15, ty = tid >> 4;

    int arow = tid >> 1, acg  = (tid & 1) * 4;
    int brow = tid >> 5, bcol = (tid & 31) * 4;

    const float* Ap = A  + (size_t)(by * 128 + arow) * K + acg;
    const float* Bp = Bm + (size_t)brow * N + bx * 128 + bcol;

    float acc[8][8];
    #pragma unroll
    for (int i = 0; i < 8; i++)
        #pragma unroll
        for (int j = 0; j < 8; j++) acc[i][j] = 0.0f;

    for (int k0 = 0; k0 < K; k0 += 8) {
        float4 a  = *(const float4*)Ap;  Ap += 8;
        float4 bv = *(const float4*)Bp;  Bp += (size_t)8 * N;

        As[acg + 0][arow] = a.x;
        As[acg + 1][arow] = a.y;
        As[acg + 2][arow] = a.z;
        As[acg + 3][arow] = a.w;
        *(float4*)&Bs[brow][bcol] = bv;
        __syncthreads();

        #pragma unroll
        for (int k = 0; k < 8; k++) {
            float ar[8], br[8];
            *(float4*)(ar)     = *(const float4*)&As[k][ty * 8];
            *(float4*)(ar + 4) = *(const float4*)&As[k][ty * 8 + 4];
            *(float4*)(br)     = *(const float4*)&Bs[k][tx * 8];
            *(float4*)(br + 4) = *(const float4*)&Bs[k][tx * 8 + 4];
            #pragma unroll
            for (int i = 0; i < 8; i++)
                #pragma unroll
                for (int j = 0; j < 8; j++)
                    acc[i][j] += ar[i] * br[j];
        }
        __syncthreads();
    }

    int row0 = by * 128 + ty * 8;
    int col0 = bx * 128 + tx * 8;
    #pragma unroll
    for (int i = 0; i < 8; i++) {
        #pragma unroll
        for (int jg = 0; jg < 8; jg += 4) {
            float4 v = make_float4(acc[i][jg], acc[i][jg+1], acc[i][jg+2], acc[i][jg+3]);
            float4 bb = *(const float4*)(bias + col0 + jg);
            v.x += bb.x; v.y += bb.y; v.z += bb.z; v.w += bb.w;
            if (MODE == 1) {
                float4 r = *(const float4*)(res + (size_t)(row0 + i) * N + col0 + jg);
                v.x += r.x; v.y += r.y; v.z += r.z; v.w += r.w;
            }
            if (MODE == 2) {
                v.x = gelu_f(v.x); v.y = gelu_f(v.y); v.z = gelu_f(v.z); v.w = gelu_f(v.w);
            }
            *(float4*)(C + (size_t)(row0 + i) * N + col0 + jg) = v;
        }
    }
}

// ---------------- flash-style causal attention, fp32 ----------------
// grid (SEQ/64, NHEAD, BATCH), 256 threads; 64-query tile; K-smem reused for P.
// XOR-4 swizzle on the K/P tile keeps total static smem at exactly 48KB.
#define KS(r, c) Ks[((r) << 6) + (((c)) ^ ((r) & 60))]

__global__ __launch_bounds__(256) void attn_kernel(const float* __restrict__ qkv,
                                                   float* __restrict__ out)
{
    __shared__ float Qs[64 * 64];
    __shared__ float Ks[64 * 64];   // holds K tile, then P tile (swizzled)
    __shared__ float Vs[64 * 64];

    int tid = threadIdx.x;
    int tx = tid & 15, ty = tid >> 4;
    int qb = blockIdx.x, h = blockIdx.y, b = blockIdx.z;

    const float* base  = qkv + (size_t)b * SEQ * (3 * D_MODEL) + h * HD;
    const float* qbase = base + (size_t)(qb * 64) * (3 * D_MODEL);

    #pragma unroll
    for (int i = 0; i < 4; i++) {
        int idx = i * 256 + tid;
        int r = idx >> 4, c4 = (idx & 15) * 4;
        *(float4*)(Qs + r * 64 + c4) =
            *(const float4*)(qbase + (size_t)r * (3 * D_MODEL) + c4);
    }

    float o[4][4];
    #pragma unroll
    for (int i = 0; i < 4; i++)
        #pragma unroll
        for (int j = 0; j < 4; j++) o[i][j] = 0.0f;
    float mrow[4] = {-INFINITY, -INFINITY, -INFINITY, -INFINITY};
    float lrow[4] = {0.0f, 0.0f, 0.0f, 0.0f};

    for (int kb = 0; kb <= qb; kb++) {
        const float* kbase = base + (size_t)(kb * 64) * (3 * D_MODEL) + D_MODEL;
        const float* vbase = kbase + D_MODEL;
        __syncthreads();   // previous iter's P/V fully consumed
        #pragma unroll
        for (int i = 0; i < 4; i++) {
            int idx = i * 256 + tid;
            int r = idx >> 4, c4 = (idx & 15) * 4;
            float4 kv = *(const float4*)(kbase + (size_t)r * (3 * D_MODEL) + c4);
            *(float4*)&KS(r, c4) = kv;    // swizzled group-of-4 stays contiguous
            *(float4*)(Vs + r * 64 + c4) =
                *(const float4*)(vbase + (size_t)r * (3 * D_MODEL) + c4);
        }
        __syncthreads();

        float s[4][4];
        #pragma unroll
        for (int i = 0; i < 4; i++)
            #pragma unroll
            for (int j = 0; j < 4; j++) s[i][j] = 0.0f;

        #pragma unroll 4
        for (int kk = 0; kk < 64; kk++) {
            float qf[4], kf[4];
            #pragma unroll
            for (int i = 0; i < 4; i++) qf[i] = Qs[(ty * 4 + i) * 64 + kk];
            #pragma unroll
            for (int j = 0; j < 4; j++) kf[j] = KS(tx * 4 + j, kk);
            #pragma unroll
            for (int i = 0; i < 4; i++)
                #pragma unroll
                for (int j = 0; j < 4; j++)
                    s[i][j] += qf[i] * kf[j];
        }

        const float scale = 0.125f;  // 1/sqrt(64)
        bool diag = (kb == qb);
        #pragma unroll
        for (int i = 0; i < 4; i++)
            #pragma unroll
            for (int j = 0; j < 4; j++) {
                float v = s[i][j] * scale;
                if (diag && (tx * 4 + j > ty * 4 + i)) v = -1e30f;
                s[i][j] = v;
            }

        #pragma unroll
        for (int i = 0; i < 4; i++) {
            float rm = fmaxf(fmaxf(s[i][0], s[i][1]), fmaxf(s[i][2], s[i][3]));
            rm = fmaxf(rm, __shfl_xor_sync(0xffffffffu, rm, 1));
            rm = fmaxf(rm, __shfl_xor_sync(0xffffffffu, rm, 2));
            rm = fmaxf(rm, __shfl_xor_sync(0xffffffffu, rm, 4));
            rm = fmaxf(rm, __shfl_xor_sync(0xffffffffu, rm, 8));
            float mnew = fmaxf(mrow[i], rm);
            float corr = __expf(mrow[i] - mnew);
            float rs = 0.0f;
            #pragma unroll
            for (int j = 0; j < 4; j++) {
                float p = __expf(s[i][j] - mnew);
                s[i][j] = p;
                rs += p;
            }
            rs += __shfl_xor_sync(0xffffffffu, rs, 1);
            rs += __shfl_xor_sync(0xffffffffu, rs, 2);
            rs += __shfl_xor_sync(0xffffffffu, rs, 4);
            rs += __shfl_xor_sync(0xffffffffu, rs, 8);
            lrow[i] = lrow[i] * corr + rs;
            mrow[i] = mnew;
            #pragma unroll
            for (int j = 0; j < 4; j++) o[i][j] *= corr;
        }

        __syncthreads();   // all done reading K tile before overwriting with P
        #pragma unroll
        for (int i = 0; i < 4; i++)
            #pragma unroll
            for (int j = 0; j < 4; j++)
                KS(ty * 4 + i, tx * 4 + j) = s[i][j];
        __syncthreads();

        #pragma unroll 4
        for (int kk = 0; kk < 64; kk++) {
            float pf[4], vf[4];
            #pragma unroll
            for (int i = 0; i < 4; i++) pf[i] = KS(ty * 4 + i, kk);
            #pragma unroll
            for (int j = 0; j < 4; j++) vf[j] = Vs[kk * 64 + tx * 4 + j];
            #pragma unroll
            for (int i = 0; i < 4; i++)
                #pragma unroll
                for (int j = 0; j < 4; j++)
                    o[i][j] += pf[i] * vf[j];
        }
    }

    #pragma unroll
    for (int i = 0; i < 4; i++) {
        float il = 1.0f / lrow[i];
        float4 ov = make_float4(o[i][0] * il, o[i][1] * il, o[i][2] * il, o[i][3] * il);
        size_t row = (size_t)(b * SEQ + qb * 64 + ty * 4 + i);
        *(float4*)(out + row * D_MODEL + h * HD + tx * 4) = ov;
    }
}

// ---------------- launch ----------------
extern "C" void kernel_launch(void* const* d_in, const int* in_sizes, int n_in,
                              void* d_out, int out_size)
{
    const float* x        = (const float*)d_in[0];
    const float* ln1_w    = (const float*)d_in[1];
    const float* ln1_b    = (const float*)d_in[2];
    const float* c_attn_w = (const float*)d_in[3];
    const float* c_attn_b = (const float*)d_in[4];
    const float* c_proj_w = (const float*)d_in[5];
    const float* c_proj_b = (const float*)d_in[6];
    const float* ln2_w    = (const float*)d_in[7];
    const float* ln2_b    = (const float*)d_in[8];
    const float* fc_w     = (const float*)d_in[9];
    const float* fc_b     = (const float*)d_in[10];
    const float* proj_w   = (const float*)d_in[11];
    const float* proj_b   = (const float*)d_in[12];
    float* out = (float*)d_out;

    float *ln1, *qkv, *attn, *x1, *ln2o, *hbuf;
    cudaGetSymbolAddress((void**)&ln1,  g_ln1);
    cudaGetSymbolAddress((void**)&qkv,  g_qkv);
    cudaGetSymbolAddress((void**)&attn, g_attn);
    cudaGetSymbolAddress((void**)&x1,   g_x1);
    cudaGetSymbolAddress((void**)&ln2o, g_ln2);
    cudaGetSymbolAddress((void**)&hbuf, g_h);

    // 1. LN1
    ln_kernel<<<NTOK, 256>>>(x, ln1_w, ln1_b, ln1);
    // 2. QKV = ln1 @ W_qkv + b   [4096 x 3072]
    gemm_kernel<0><<<dim3(3 * D_MODEL / 128, NTOK / 128), 256>>>(
        ln1, c_attn_w, c_attn_b, nullptr, qkv, NTOK, 3 * D_MODEL, D_MODEL);
    // 3. causal attention
    attn_kernel<<<dim3(SEQ / 64, NHEAD, BATCH), 256>>>(qkv, attn);
    // 4. x1 = x + attn @ W_proj + b   [4096 x 1024]
    gemm_kernel<1><<<dim3(D_MODEL / 128, NTOK / 128), 256>>>(
        attn, c_proj_w, c_proj_b, x, x1, NTOK, D_MODEL, D_MODEL);
    // 5. LN2
    ln_kernel<<<NTOK, 256>>>(x1, ln2_w, ln2_b, ln2o);
    // 6. h = gelu(ln2 @ W_fc + b)   [4096 x 4096]
    gemm_kernel<2><<<dim3(4 * D_MODEL / 128, NTOK / 128), 256>>>(
        ln2o, fc_w, fc_b, nullptr, hbuf, NTOK, 4 * D_MODEL, D_MODEL);
    // 7. out = x1 + h @ W_proj2 + b   [4096 x 1024]
    gemm_kernel<1><<<dim3(D_MODEL / 128, NTOK / 128), 256>>>(
        hbuf, proj_w, proj_b, x1, out, NTOK, D_MODEL, 4 * D_MODEL);
}

// round 2
// speedup vs baseline: 2.0715x; 2.0715x over previous
#include <cuda_runtime.h>
#include <math.h>
#include <stdint.h>

#define D_MODEL 1024
#define SEQ     2048
#define BATCH   2
#define NTOK    4096   // BATCH*SEQ
#define NHEAD   16
#define HD      64

// ---------------- scratch (no allocations allowed) ----------------
__device__ float g_ln1 [NTOK * D_MODEL];
__device__ float g_qkv [NTOK * 3 * D_MODEL];
__device__ float g_attn[NTOK * D_MODEL];
__device__ float g_x1  [NTOK * D_MODEL];
__device__ float g_ln2 [NTOK * D_MODEL];
__device__ float g_h   [NTOK * 4 * D_MODEL];

// ---------------- LayerNorm (torch-style: Bessel std, eps on std) ----------------
__global__ __launch_bounds__(256) void ln_kernel(const float* __restrict__ x,
                                                 const float* __restrict__ w,
                                                 const float* __restrict__ b,
                                                 float* __restrict__ y)
{
    int row = blockIdx.x;
    int tid = threadIdx.x;
    const float4* xr = (const float4*)(x + (size_t)row * D_MODEL);
    float4 v = xr[tid];

    __shared__ float red[8];

    float s = v.x + v.y + v.z + v.w;
    #pragma unroll
    for (int o = 16; o > 0; o >>= 1) s += __shfl_xor_sync(0xffffffffu, s, o);
    if ((tid & 31) == 0) red[tid >> 5] = s;
    __syncthreads();
    float tot = red[0] + red[1] + red[2] + red[3] + red[4] + red[5] + red[6] + red[7];
    float mean = tot * (1.0f / 1024.0f);

    float a0 = v.x - mean, a1 = v.y - mean, a2 = v.z - mean, a3 = v.w - mean;
    __syncthreads();
    float q = a0*a0 + a1*a1 + a2*a2 + a3*a3;
    #pragma unroll
    for (int o = 16; o > 0; o >>= 1) q += __shfl_xor_sync(0xffffffffu, q, o);
    if ((tid & 31) == 0) red[tid >> 5] = q;
    __syncthreads();
    float ssq = red[0] + red[1] + red[2] + red[3] + red[4] + red[5] + red[6] + red[7];

    float sd  = sqrtf(ssq * (1.0f / 1023.0f));
    float inv = 1.0f / (sd + 1e-5f);

    float4 wv = ((const float4*)w)[tid];
    float4 bv = ((const float4*)b)[tid];
    float4 o;
    o.x = wv.x * (a0 * inv) + bv.x;
    o.y = wv.y * (a1 * inv) + bv.y;
    o.z = wv.z * (a2 * inv) + bv.z;
    o.w = wv.w * (a3 * inv) + bv.w;
    ((float4*)(y + (size_t)row * D_MODEL))[tid] = o;
}

// ---------------- GELU ----------------
__device__ __forceinline__ float gelu_f(float x)
{
    float x3 = x * x * x;
    return 0.5f * x * (1.0f + tanhf(0.7978845608028654f * (x + 0.044715f * x3)));
}

// ---------------- tf32 tensor-core GEMM, 128x128x32 tiles ----------------
__device__ __forceinline__ uint32_t f2tf(float x)
{
    uint32_t r;
    asm("cvt.rna.tf32.f32 %0, %1;\n" : "=r"(r) : "f"(x));
    return r;
}

__device__ __forceinline__ void cp16(uint32_t dst, const void* src)
{
    asm volatile("cp.async.cg.shared.global [%0], [%1], 16;\n" :: "r"(dst), "l"(src));
}

#define BM 128
#define BN 128
#define BKT 32
#define AS_STRIDE 36      // floats: bank = (4m + k) % 32 -> conflict-free A frags
#define BS_STRIDE 136     // floats: bank = (8k + n) % 32 -> conflict-free B frags
#define AS_FLOATS (BM * AS_STRIDE)          // 4608
#define BS_FLOATS (BKT * BS_STRIDE)         // 4352
#define STAGE_FLOATS (AS_FLOATS + BS_FLOATS)
#define GEMM_SMEM_BYTES (2 * STAGE_FLOATS * 4)   // 71680

// MODE 0: C = A@B + bias ; MODE 1: += res ; MODE 2: gelu(...)
template<int MODE>
__global__ __launch_bounds__(256, 2) void gemm_tc(const float* __restrict__ A,
                                                  const float* __restrict__ Bm,
                                                  const float* __restrict__ bias,
                                                  const float* __restrict__ res,
                                                  float* __restrict__ C,
                                                  int M, int N, int K)
{
    extern __shared__ float sm[];
    int tid  = threadIdx.x;
    int bx = blockIdx.x, by = blockIdx.y;
    int warp = tid >> 5, lane = tid & 31;
    int wm = warp >> 2, wn = warp & 3;          // 2 x 4 warps -> 64x32 warp tiles
    int g = lane >> 2, tig = lane & 3;

    const float* Ablk = A + (size_t)(by * BM) * K;
    const float* Bblk = Bm + bx * BN;

    float c[4][4][4];
    #pragma unroll
    for (int mt = 0; mt < 4; mt++)
        #pragma unroll
        for (int nt = 0; nt < 4; nt++)
            #pragma unroll
            for (int r = 0; r < 4; r++) c[mt][nt][r] = 0.0f;

    const int iters = K / BKT;
    uint32_t smem_base = (uint32_t)__cvta_generic_to_shared(sm);

    // async load of stage `buf` covering k0
    auto load_stage = [&](int it, int buf) {
        uint32_t as = smem_base + (uint32_t)(buf * STAGE_FLOATS) * 4u;
        uint32_t bs = as + (uint32_t)AS_FLOATS * 4u;
        int k0 = it * BKT;
        #pragma unroll
        for (int i = 0; i < 4; i++) {
            int q = tid + 256 * i;          // 0..1023
            int ar = q >> 3, ac = (q & 7) * 4;
            cp16(as + (uint32_t)(ar * AS_STRIDE + ac) * 4u,
                 Ablk + (size_t)ar * K + k0 + ac);
            int br = q >> 5, bc = (q & 31) * 4;
            cp16(bs + (uint32_t)(br * BS_STRIDE + bc) * 4u,
                 Bblk + (size_t)(k0 + br) * N + bc);
        }
        asm volatile("cp.async.commit_group;\n" ::: "memory");
    };

    load_stage(0, 0);

    for (int it = 0; it < iters; it++) {
        if (it + 1 < iters) {
            load_stage(it + 1, (it + 1) & 1);
            asm volatile("cp.async.wait_group 1;\n" ::: "memory");
        } else {
            asm volatile("cp.async.wait_group 0;\n" ::: "memory");
        }
        __syncthreads();

        const float* As = sm + (it & 1) * STAGE_FLOATS;
        const float* Bs = As + AS_FLOATS;

        #pragma unroll
        for (int kk = 0; kk < 4; kk++) {
            int kb = kk * 8;
            uint32_t a[4][4], b[4][2];
            #pragma unroll
            for (int mt = 0; mt < 4; mt++) {
                int m = wm * 64 + mt * 16 + g;
                a[mt][0] = f2tf(As[m * AS_STRIDE + kb + tig]);
                a[mt][1] = f2tf(As[(m + 8) * AS_STRIDE + kb + tig]);
                a[mt][2] = f2tf(As[m * AS_STRIDE + kb + tig + 4]);
                a[mt][3] = f2tf(As[(m + 8) * AS_STRIDE + kb + tig + 4]);
            }
            #pragma unroll
            for (int nt = 0; nt < 4; nt++) {
                int n = wn * 32 + nt * 8 + g;
                b[nt][0] = f2tf(Bs[(kb + tig) * BS_STRIDE + n]);
                b[nt][1] = f2tf(Bs[(kb + tig + 4) * BS_STRIDE + n]);
            }
            #pragma unroll
            for (int mt = 0; mt < 4; mt++)
                #pragma unroll
                for (int nt = 0; nt < 4; nt++)
                    asm volatile(
                        "mma.sync.aligned.m16n8k8.row.col.f32.tf32.tf32.f32 "
                        "{%0,%1,%2,%3}, {%4,%5,%6,%7}, {%8,%9}, {%0,%1,%2,%3};\n"
                        : "+f"(c[mt][nt][0]), "+f"(c[mt][nt][1]),
                          "+f"(c[mt][nt][2]), "+f"(c[mt][nt][3])
                        : "r"(a[mt][0]), "r"(a[mt][1]), "r"(a[mt][2]), "r"(a[mt][3]),
                          "r"(b[nt][0]), "r"(b[nt][1]));
        }
        __syncthreads();
    }

    // epilogue
    #pragma unroll
    for (int mt = 0; mt < 4; mt++) {
        int row0 = by * BM + wm * 64 + mt * 16 + g;
        #pragma unroll
        for (int nt = 0; nt < 4; nt++) {
            int col = bx * BN + wn * 32 + nt * 8 + tig * 2;
            float b0 = __ldg(bias + col), b1 = __ldg(bias + col + 1);
            float v0 = c[mt][nt][0] + b0, v1 = c[mt][nt][1] + b1;
            float v2 = c[mt][nt][2] + b0, v3 = c[mt][nt][3] + b1;
            if (MODE == 1) {
                const float* r0 = res + (size_t)row0 * N + col;
                const float* r1 = res + (size_t)(row0 + 8) * N + col;
                v0 += r0[0]; v1 += r0[1];
                v2 += r1[0]; v3 += r1[1];
            }
            if (MODE == 2) {
                v0 = gelu_f(v0); v1 = gelu_f(v1);
                v2 = gelu_f(v2); v3 = gelu_f(v3);
            }
            *(float2*)(C + (size_t)row0 * N + col)       = make_float2(v0, v1);
            *(float2*)(C + (size_t)(row0 + 8) * N + col) = make_float2(v2, v3);
        }
    }
}

// ---------------- flash-style causal attention, fp32 (unchanged) ----------------
#define KS(r, c) Ks[((r) << 6) + (((c)) ^ ((r) & 60))]

__global__ __launch_bounds__(256) void attn_kernel(const float* __restrict__ qkv,
                                                   float* __restrict__ out)
{
    __shared__ float Qs[64 * 64];
    __shared__ float Ks[64 * 64];
    __shared__ float Vs[64 * 64];

    int tid = threadIdx.x;
    int tx = tid & 15, ty = tid >> 4;
    int qb = blockIdx.x, h = blockIdx.y, b = blockIdx.z;

    const float* base  = qkv + (size_t)b * SEQ * (3 * D_MODEL) + h * HD;
    const float* qbase = base + (size_t)(qb * 64) * (3 * D_MODEL);

    #pragma unroll
    for (int i = 0; i < 4; i++) {
        int idx = i * 256 + tid;
        int r = idx >> 4, c4 = (idx & 15) * 4;
        *(float4*)(Qs + r * 64 + c4) =
            *(const float4*)(qbase + (size_t)r * (3 * D_MODEL) + c4);
    }

    float o[4][4];
    #pragma unroll
    for (int i = 0; i < 4; i++)
        #pragma unroll
        for (int j = 0; j < 4; j++) o[i][j] = 0.0f;
    float mrow[4] = {-INFINITY, -INFINITY, -INFINITY, -INFINITY};
    float lrow[4] = {0.0f, 0.0f, 0.0f, 0.0f};

    for (int kb = 0; kb <= qb; kb++) {
        const float* kbase = base + (size_t)(kb * 64) * (3 * D_MODEL) + D_MODEL;
        const float* vbase = kbase + D_MODEL;
        __syncthreads();
        #pragma unroll
        for (int i = 0; i < 4; i++) {
            int idx = i * 256 + tid;
            int r = idx >> 4, c4 = (idx & 15) * 4;
            float4 kv = *(const float4*)(kbase + (size_t)r * (3 * D_MODEL) + c4);
            *(float4*)&KS(r, c4) = kv;
            *(float4*)(Vs + r * 64 + c4) =
                *(const float4*)(vbase + (size_t)r * (3 * D_MODEL) + c4);
        }
        __syncthreads();

        float s[4][4];
        #pragma unroll
        for (int i = 0; i < 4; i++)
            #pragma unroll
            for (int j = 0; j < 4; j++) s[i][j] = 0.0f;

        #pragma unroll 4
        for (int kk = 0; kk < 64; kk++) {
            float qf[4], kf[4];
            #pragma unroll
            for (int i = 0; i < 4; i++) qf[i] = Qs[(ty * 4 + i) * 64 + kk];
            #pragma unroll
            for (int j = 0; j < 4; j++) kf[j] = KS(tx * 4 + j, kk);
            #pragma unroll
            for (int i = 0; i < 4; i++)
                #pragma unroll
                for (int j = 0; j < 4; j++)
                    s[i][j] += qf[i] * kf[j];
        }

        const float scale = 0.125f;
        bool diag = (kb == qb);
        #pragma unroll
        for (int i = 0; i < 4; i++)
            #pragma unroll
            for (int j = 0; j < 4; j++) {
                float v = s[i][j] * scale;
                if (diag && (tx * 4 + j > ty * 4 + i)) v = -1e30f;
                s[i][j] = v;
            }

        #pragma unroll
        for (int i = 0; i < 4; i++) {
            float rm = fmaxf(fmaxf(s[i][0], s[i][1]), fmaxf(s[i][2], s[i][3]));
            rm = fmaxf(rm, __shfl_xor_sync(0xffffffffu, rm, 1));
            rm = fmaxf(rm, __shfl_xor_sync(0xffffffffu, rm, 2));
            rm = fmaxf(rm, __shfl_xor_sync(0xffffffffu, rm, 4));
            rm = fmaxf(rm, __shfl_xor_sync(0xffffffffu, rm, 8));
            float mnew = fmaxf(mrow[i], rm);
            float corr = __expf(mrow[i] - mnew);
            float rs = 0.0f;
            #pragma unroll
            for (int j = 0; j < 4; j++) {
                float p = __expf(s[i][j] - mnew);
                s[i][j] = p;
                rs += p;
            }
            rs += __shfl_xor_sync(0xffffffffu, rs, 1);
            rs += __shfl_xor_sync(0xffffffffu, rs, 2);
            rs += __shfl_xor_sync(0xffffffffu, rs, 4);
            rs += __shfl_xor_sync(0xffffffffu, rs, 8);
            lrow[i] = lrow[i] * corr + rs;
            mrow[i] = mnew;
            #pragma unroll
            for (int j = 0; j < 4; j++) o[i][j] *= corr;
        }

        __syncthreads();
        #pragma unroll
        for (int i = 0; i < 4; i++)
            #pragma unroll
            for (int j = 0; j < 4; j++)
                KS(ty * 4 + i, tx * 4 + j) = s[i][j];
        __syncthreads();

        #pragma unroll 4
        for (int kk = 0; kk < 64; kk++) {
            float pf[4], vf[4];
            #pragma unroll
            for (int i = 0; i < 4; i++) pf[i] = KS(ty * 4 + i, kk);
            #pragma unroll
            for (int j = 0; j < 4; j++) vf[j] = Vs[kk * 64 + tx * 4 + j];
            #pragma unroll
            for (int i = 0; i < 4; i++)
                #pragma unroll
                for (int j = 0; j < 4; j++)
                    o[i][j] += pf[i] * vf[j];
        }
    }

    #pragma unroll
    for (int i = 0; i < 4; i++) {
        float il = 1.0f / lrow[i];
        float4 ov = make_float4(o[i][0] * il, o[i][1] * il, o[i][2] * il, o[i][3] * il);
        size_t row = (size_t)(b * SEQ + qb * 64 + ty * 4 + i);
        *(float4*)(out + row * D_MODEL + h * HD + tx * 4) = ov;
    }
}

// ---------------- launch ----------------
extern "C" void kernel_launch(void* const* d_in, const int* in_sizes, int n_in,
                              void* d_out, int out_size)
{
    const float* x        = (const float*)d_in[0];
    const float* ln1_w    = (const float*)d_in[1];
    const float* ln1_b    = (const float*)d_in[2];
    const float* c_attn_w = (const float*)d_in[3];
    const float* c_attn_b = (const float*)d_in[4];
    const float* c_proj_w = (const float*)d_in[5];
    const float* c_proj_b = (const float*)d_in[6];
    const float* ln2_w    = (const float*)d_in[7];
    const float* ln2_b    = (const float*)d_in[8];
    const float* fc_w     = (const float*)d_in[9];
    const float* fc_b     = (const float*)d_in[10];
    const float* proj_w   = (const float*)d_in[11];
    const float* proj_b   = (const float*)d_in[12];
    float* out = (float*)d_out;

    float *ln1, *qkv, *attn, *x1, *ln2o, *hbuf;
    cudaGetSymbolAddress((void**)&ln1,  g_ln1);
    cudaGetSymbolAddress((void**)&qkv,  g_qkv);
    cudaGetSymbolAddress((void**)&attn, g_attn);
    cudaGetSymbolAddress((void**)&x1,   g_x1);
    cudaGetSymbolAddress((void**)&ln2o, g_ln2);
    cudaGetSymbolAddress((void**)&hbuf, g_h);

    static bool attr_done = false;
    if (!attr_done) {
        cudaFuncSetAttribute(gemm_tc<0>, cudaFuncAttributeMaxDynamicSharedMemorySize, GEMM_SMEM_BYTES);
        cudaFuncSetAttribute(gemm_tc<1>, cudaFuncAttributeMaxDynamicSharedMemorySize, GEMM_SMEM_BYTES);
        cudaFuncSetAttribute(gemm_tc<2>, cudaFuncAttributeMaxDynamicSharedMemorySize, GEMM_SMEM_BYTES);
        attr_done = true;
    }

    // 1. LN1
    ln_kernel<<<NTOK, 256>>>(x, ln1_w, ln1_b, ln1);
    // 2. QKV = ln1 @ W_qkv + b   [4096 x 3072, K=1024]
    gemm_tc<0><<<dim3(3 * D_MODEL / BN, NTOK / BM), 256, GEMM_SMEM_BYTES>>>(
        ln1, c_attn_w, c_attn_b, nullptr, qkv, NTOK, 3 * D_MODEL, D_MODEL);
    // 3. causal attention
    attn_kernel<<<dim3(SEQ / 64, NHEAD, BATCH), 256>>>(qkv, attn);
    // 4. x1 = x + attn @ W_proj + b   [4096 x 1024, K=1024]
    gemm_tc<1><<<dim3(D_MODEL / BN, NTOK / BM), 256, GEMM_SMEM_BYTES>>>(
        attn, c_proj_w, c_proj_b, x, x1, NTOK, D_MODEL, D_MODEL);
    // 5. LN2
    ln_kernel<<<NTOK, 256>>>(x1, ln2_w, ln2_b, ln2o);
    // 6. h = gelu(ln2 @ W_fc + b)   [4096 x 4096, K=1024]
    gemm_tc<2><<<dim3(4 * D_MODEL / BN, NTOK / BM), 256, GEMM_SMEM_BYTES>>>(
        ln2o, fc_w, fc_b, nullptr, hbuf, NTOK, 4 * D_MODEL, D_MODEL);
    // 7. out = x1 + h @ W_proj2 + b   [4096 x 1024, K=4096]
    gemm_tc<1><<<dim3(D_MODEL / BN, NTOK / BM), 256, GEMM_SMEM_BYTES>>>(
        hbuf, proj_w, proj_b, x1, out, NTOK, D_MODEL, 4 * D_MODEL);
}

// round 3
// speedup vs baseline: 3.8253x; 1.8467x over previous
#include <cuda_runtime.h>
#include <math.h>
#include <stdint.h>

#define D_MODEL 1024
#define SEQ     2048
#define BATCH   2
#define NTOK    4096
#define NHEAD   16
#define HD      64

// ---------------- scratch ----------------
__device__ float g_ln1 [NTOK * D_MODEL];
__device__ float g_qkv [NTOK * 3 * D_MODEL];
__device__ float g_attn[NTOK * D_MODEL];
__device__ float g_x1  [NTOK * D_MODEL];
__device__ float g_ln2 [NTOK * D_MODEL];
__device__ float g_h   [NTOK * 4 * D_MODEL];

// ---------------- LayerNorm ----------------
__global__ __launch_bounds__(256) void ln_kernel(const float* __restrict__ x,
                                                 const float* __restrict__ w,
                                                 const float* __restrict__ b,
                                                 float* __restrict__ y)
{
    int row = blockIdx.x;
    int tid = threadIdx.x;
    const float4* xr = (const float4*)(x + (size_t)row * D_MODEL);
    float4 v = xr[tid];

    __shared__ float red[8];

    float s = v.x + v.y + v.z + v.w;
    #pragma unroll
    for (int o = 16; o > 0; o >>= 1) s += __shfl_xor_sync(0xffffffffu, s, o);
    if ((tid & 31) == 0) red[tid >> 5] = s;
    __syncthreads();
    float tot = red[0] + red[1] + red[2] + red[3] + red[4] + red[5] + red[6] + red[7];
    float mean = tot * (1.0f / 1024.0f);

    float a0 = v.x - mean, a1 = v.y - mean, a2 = v.z - mean, a3 = v.w - mean;
    __syncthreads();
    float q = a0*a0 + a1*a1 + a2*a2 + a3*a3;
    #pragma unroll
    for (int o = 16; o > 0; o >>= 1) q += __shfl_xor_sync(0xffffffffu, q, o);
    if ((tid & 31) == 0) red[tid >> 5] = q;
    __syncthreads();
    float ssq = red[0] + red[1] + red[2] + red[3] + red[4] + red[5] + red[6] + red[7];

    float sd  = sqrtf(ssq * (1.0f / 1023.0f));
    float inv = 1.0f / (sd + 1e-5f);

    float4 wv = ((const float4*)w)[tid];
    float4 bv = ((const float4*)b)[tid];
    float4 o;
    o.x = wv.x * (a0 * inv) + bv.x;
    o.y = wv.y * (a1 * inv) + bv.y;
    o.z = wv.z * (a2 * inv) + bv.z;
    o.w = wv.w * (a3 * inv) + bv.w;
    ((float4*)(y + (size_t)row * D_MODEL))[tid] = o;
}

__device__ __forceinline__ float gelu_f(float x)
{
    float x3 = x * x * x;
    return 0.5f * x * (1.0f + tanhf(0.7978845608028654f * (x + 0.044715f * x3)));
}

// raw fp32 bits as tf32 operand (HW ignores low 13 mantissa bits)
__device__ __forceinline__ uint32_t f2tf(float x) { return __float_as_uint(x); }

__device__ __forceinline__ void cp16(uint32_t dst, const void* src)
{
    asm volatile("cp.async.cg.shared.global [%0], [%1], 16;\n" :: "r"(dst), "l"(src));
}

#define MMA_TF32(c, a, b) \
    asm volatile( \
        "mma.sync.aligned.m16n8k8.row.col.f32.tf32.tf32.f32 " \
        "{%0,%1,%2,%3}, {%4,%5,%6,%7}, {%8,%9}, {%0,%1,%2,%3};\n" \
        : "+f"((c)[0]), "+f"((c)[1]), "+f"((c)[2]), "+f"((c)[3]) \
        : "r"((a)[0]), "r"((a)[1]), "r"((a)[2]), "r"((a)[3]), \
          "r"((b)[0]), "r"((b)[1]))

// ---------------- tf32 GEMM 128x128x32 ----------------
#define BM 128
#define BN 128
#define BKT 32
#define AS_STRIDE 36
#define BS_STRIDE 136
#define AS_FLOATS (BM * AS_STRIDE)
#define BS_FLOATS (BKT * BS_STRIDE)
#define STAGE_FLOATS (AS_FLOATS + BS_FLOATS)
#define GEMM_SMEM_BYTES (2 * STAGE_FLOATS * 4)

template<int MODE>
__global__ __launch_bounds__(256, 2) void gemm_tc(const float* __restrict__ A,
                                                  const float* __restrict__ Bm,
                                                  const float* __restrict__ bias,
                                                  const float* __restrict__ res,
                                                  float* __restrict__ C,
                                                  int M, int N, int K)
{
    extern __shared__ float sm[];
    int tid  = threadIdx.x;
    int bx = blockIdx.x, by = blockIdx.y;
    int warp = tid >> 5, lane = tid & 31;
    int wm = warp >> 2, wn = warp & 3;
    int g = lane >> 2, tig = lane & 3;

    const float* Ablk = A + (size_t)(by * BM) * K;
    const float* Bblk = Bm + bx * BN;

    float c[4][4][4];
    #pragma unroll
    for (int mt = 0; mt < 4; mt++)
        #pragma unroll
        for (int nt = 0; nt < 4; nt++)
            #pragma unroll
            for (int r = 0; r < 4; r++) c[mt][nt][r] = 0.0f;

    const int iters = K / BKT;
    uint32_t smem_base = (uint32_t)__cvta_generic_to_shared(sm);

    auto load_stage = [&](int it, int buf) {
        uint32_t as = smem_base + (uint32_t)(buf * STAGE_FLOATS) * 4u;
        uint32_t bs = as + (uint32_t)AS_FLOATS * 4u;
        int k0 = it * BKT;
        #pragma unroll
        for (int i = 0; i < 4; i++) {
            int q = tid + 256 * i;
            int ar = q >> 3, ac = (q & 7) * 4;
            cp16(as + (uint32_t)(ar * AS_STRIDE + ac) * 4u,
                 Ablk + (size_t)ar * K + k0 + ac);
            int br = q >> 5, bc = (q & 31) * 4;
            cp16(bs + (uint32_t)(br * BS_STRIDE + bc) * 4u,
                 Bblk + (size_t)(k0 + br) * N + bc);
        }
        asm volatile("cp.async.commit_group;\n" ::: "memory");
    };

    load_stage(0, 0);

    for (int it = 0; it < iters; it++) {
        if (it + 1 < iters) {
            load_stage(it + 1, (it + 1) & 1);
            asm volatile("cp.async.wait_group 1;\n" ::: "memory");
        } else {
            asm volatile("cp.async.wait_group 0;\n" ::: "memory");
        }
        __syncthreads();

        const float* As = sm + (it & 1) * STAGE_FLOATS;
        const float* Bs = As + AS_FLOATS;

        #pragma unroll
        for (int kk = 0; kk < 4; kk++) {
            int kb = kk * 8;
            uint32_t a[4][4], b[4][2];
            #pragma unroll
            for (int mt = 0; mt < 4; mt++) {
                int m = wm * 64 + mt * 16 + g;
                a[mt][0] = f2tf(As[m * AS_STRIDE + kb + tig]);
                a[mt][1] = f2tf(As[(m + 8) * AS_STRIDE + kb + tig]);
                a[mt][2] = f2tf(As[m * AS_STRIDE + kb + tig + 4]);
                a[mt][3] = f2tf(As[(m + 8) * AS_STRIDE + kb + tig + 4]);
            }
            #pragma unroll
            for (int nt = 0; nt < 4; nt++) {
                int n = wn * 32 + nt * 8 + g;
                b[nt][0] = f2tf(Bs[(kb + tig) * BS_STRIDE + n]);
                b[nt][1] = f2tf(Bs[(kb + tig + 4) * BS_STRIDE + n]);
            }
            #pragma unroll
            for (int mt = 0; mt < 4; mt++)
                #pragma unroll
                for (int nt = 0; nt < 4; nt++)
                    MMA_TF32(c[mt][nt], a[mt], b[nt]);
        }
        __syncthreads();
    }

    #pragma unroll
    for (int mt = 0; mt < 4; mt++) {
        int row0 = by * BM + wm * 64 + mt * 16 + g;
        #pragma unroll
        for (int nt = 0; nt < 4; nt++) {
            int col = bx * BN + wn * 32 + nt * 8 + tig * 2;
            float b0 = __ldg(bias + col), b1 = __ldg(bias + col + 1);
            float v0 = c[mt][nt][0] + b0, v1 = c[mt][nt][1] + b1;
            float v2 = c[mt][nt][2] + b0, v3 = c[mt][nt][3] + b1;
            if (MODE == 1) {
                const float* r0 = res + (size_t)row0 * N + col;
                const float* r1 = res + (size_t)(row0 + 8) * N + col;
                v0 += r0[0]; v1 += r0[1];
                v2 += r1[0]; v3 += r1[1];
            }
            if (MODE == 2) {
                v0 = gelu_f(v0); v1 = gelu_f(v1);
                v2 = gelu_f(v2); v3 = gelu_f(v3);
            }
            *(float2*)(C + (size_t)row0 * N + col)       = make_float2(v0, v1);
            *(float2*)(C + (size_t)(row0 + 8) * N + col) = make_float2(v2, v3);
        }
    }
}

// ---------------- tensor-core flash attention ----------------
// 128 q-rows per block, 64-key tiles, 8 warps (each warp: 16 q-rows x all 64 cols).
// Layouts (floats): Qs[128][QS_STR], Ks[64][KS_STR], Vs[64][VS_STR], Ps[128][PS_STR]
// Strides chosen so all fragment LDS are bank-conflict-free:
//   A-pattern (stride%32==4): bank = 4*g + tig ; B-K pattern (stride%32==4): 4g+tig
//   B-V pattern (stride%32==8): bank = 8*tig + g
#define QT 128
#define KT 64
#define QS_STR 68
#define KS_STR 68
#define VS_STR 72
#define PS_STR 68
#define ATTN_SMEM ((QT*QS_STR + KT*KS_STR + KT*VS_STR + QT*PS_STR) * 4)

__global__ __launch_bounds__(256, 2) void attn_tc(const float* __restrict__ qkv,
                                                  float* __restrict__ out)
{
    extern __shared__ float sm[];
    float* Qs = sm;
    float* Ks = Qs + QT * QS_STR;
    float* Vs = Ks + KT * KS_STR;
    float* Ps = Vs + KT * VS_STR;

    int tid = threadIdx.x, warp = tid >> 5, lane = tid & 31;
    int g = lane >> 2, tig = lane & 3;
    int qb = blockIdx.x, h = blockIdx.y, b = blockIdx.z;

    const float* base = qkv + (size_t)b * SEQ * (3 * D_MODEL) + h * HD;

    uint32_t qs_u = (uint32_t)__cvta_generic_to_shared(Qs);
    uint32_t ks_u = (uint32_t)__cvta_generic_to_shared(Ks);
    uint32_t vs_u = (uint32_t)__cvta_generic_to_shared(Vs);

    // Q tile: 128 x 64
    #pragma unroll
    for (int i = 0; i < 8; i++) {
        int idx = i * 256 + tid;
        int r = idx >> 4, d4 = (idx & 15) * 4;
        cp16(qs_u + (uint32_t)(r * QS_STR + d4) * 4u,
             base + (size_t)(qb * QT + r) * (3 * D_MODEL) + d4);
    }
    asm volatile("cp.async.commit_group;\n" ::: "memory");

    float o[8][4];
    #pragma unroll
    for (int nt = 0; nt < 8; nt++)
        #pragma unroll
        for (int r = 0; r < 4; r++) o[nt][r] = 0.0f;
    float m0 = -INFINITY, m1 = -INFINITY, l0 = 0.0f, l1 = 0.0f;

    int qrow_lo = qb * QT + warp * 16;      // warp's first q row
    int kb_end = 2 * qb + 1;

    for (int kb = 0; kb <= kb_end; kb++) {
        __syncthreads();   // everyone done with previous K/V
        #pragma unroll
        for (int i = 0; i < 4; i++) {
            int idx = i * 256 + tid;
            int r = idx >> 4, d4 = (idx & 15) * 4;
            const float* krow = base + D_MODEL + (size_t)(kb * KT + r) * (3 * D_MODEL) + d4;
            cp16(ks_u + (uint32_t)(r * KS_STR + d4) * 4u, krow);
            cp16(vs_u + (uint32_t)(r * VS_STR + d4) * 4u, krow + D_MODEL);
        }
        asm volatile("cp.async.commit_group;\n" ::: "memory");
        asm volatile("cp.async.wait_group 0;\n" ::: "memory");
        __syncthreads();

        if (kb * 64 > qrow_lo - qb * QT + qb * QT + 15 + warp * 0 &&
            kb * 64 > qb * QT + warp * 16 + 15) { continue; }  // fully masked for warp

        // ---- S = Q K^T ----
        float s[8][4];
        #pragma unroll
        for (int nt = 0; nt < 8; nt++)
            #pragma unroll
            for (int r = 0; r < 4; r++) s[nt][r] = 0.0f;

        #pragma unroll
        for (int ks = 0; ks < 8; ks++) {
            int kbq = ks * 8;
            uint32_t a[4], bb[8][2];
            int mrow = warp * 16 + g;
            a[0] = f2tf(Qs[mrow * QS_STR + kbq + tig]);
            a[1] = f2tf(Qs[(mrow + 8) * QS_STR + kbq + tig]);
            a[2] = f2tf(Qs[mrow * QS_STR + kbq + tig + 4]);
            a[3] = f2tf(Qs[(mrow + 8) * QS_STR + kbq + tig + 4]);
            #pragma unroll
            for (int nt = 0; nt < 8; nt++) {
                bb[nt][0] = f2tf(Ks[(nt * 8 + g) * KS_STR + kbq + tig]);
                bb[nt][1] = f2tf(Ks[(nt * 8 + g) * KS_STR + kbq + tig + 4]);
            }
            #pragma unroll
            for (int nt = 0; nt < 8; nt++) MMA_TF32(s[nt], a, bb[nt]);
        }

        // ---- scale + causal mask ----
        const float scale = 0.125f;
        int q0 = qb * QT + warp * 16 + g;
        int q1 = q0 + 8;
        bool diag = (kb * 64 + 63 > qrow_lo);   // tile may cross diagonal for this warp
        #pragma unroll
        for (int nt = 0; nt < 8; nt++) {
            int key = kb * 64 + nt * 8 + 2 * tig;
            s[nt][0] *= scale; s[nt][1] *= scale;
            s[nt][2] *= scale; s[nt][3] *= scale;
            if (diag) {
                if (key     > q0) s[nt][0] = -1e30f;
                if (key + 1 > q0) s[nt][1] = -1e30f;
                if (key     > q1) s[nt][2] = -1e30f;
                if (key + 1 > q1) s[nt][3] = -1e30f;
            }
        }

        // ---- online softmax (rows q0, q1 owned by this warp) ----
        float rmax0 = -INFINITY, rmax1 = -INFINITY;
        #pragma unroll
        for (int nt = 0; nt < 8; nt++) {
            rmax0 = fmaxf(rmax0, fmaxf(s[nt][0], s[nt][1]));
            rmax1 = fmaxf(rmax1, fmaxf(s[nt][2], s[nt][3]));
        }
        rmax0 = fmaxf(rmax0, __shfl_xor_sync(0xffffffffu, rmax0, 1));
        rmax0 = fmaxf(rmax0, __shfl_xor_sync(0xffffffffu, rmax0, 2));
        rmax1 = fmaxf(rmax1, __shfl_xor_sync(0xffffffffu, rmax1, 1));
        rmax1 = fmaxf(rmax1, __shfl_xor_sync(0xffffffffu, rmax1, 2));

        float mn0 = fmaxf(m0, rmax0), mn1 = fmaxf(m1, rmax1);
        float corr0 = __expf(m0 - mn0), corr1 = __expf(m1 - mn1);

        float rs0 = 0.0f, rs1 = 0.0f;
        #pragma unroll
        for (int nt = 0; nt < 8; nt++) {
            s[nt][0] = __expf(s[nt][0] - mn0);
            s[nt][1] = __expf(s[nt][1] - mn0);
            s[nt][2] = __expf(s[nt][2] - mn1);
            s[nt][3] = __expf(s[nt][3] - mn1);
            rs0 += s[nt][0] + s[nt][1];
            rs1 += s[nt][2] + s[nt][3];
        }
        rs0 += __shfl_xor_sync(0xffffffffu, rs0, 1);
        rs0 += __shfl_xor_sync(0xffffffffu, rs0, 2);
        rs1 += __shfl_xor_sync(0xffffffffu, rs1, 1);
        rs1 += __shfl_xor_sync(0xffffffffu, rs1, 2);

        l0 = l0 * corr0 + rs0;  m0 = mn0;
        l1 = l1 * corr1 + rs1;  m1 = mn1;

        // ---- P to (warp-private) smem ----
        int pr0 = warp * 16 + g;
        #pragma unroll
        for (int nt = 0; nt < 8; nt++) {
            *(float2*)&Ps[pr0 * PS_STR + nt * 8 + 2 * tig]       = make_float2(s[nt][0], s[nt][1]);
            *(float2*)&Ps[(pr0 + 8) * PS_STR + nt * 8 + 2 * tig] = make_float2(s[nt][2], s[nt][3]);
        }
        __syncwarp();

        // rescale O
        #pragma unroll
        for (int nt = 0; nt < 8; nt++) {
            o[nt][0] *= corr0; o[nt][1] *= corr0;
            o[nt][2] *= corr1; o[nt][3] *= corr1;
        }

        // ---- O += P V ----
        #pragma unroll
        for (int ks = 0; ks < 8; ks++) {
            int kbq = ks * 8;
            uint32_t a[4], bb[8][2];
            a[0] = f2tf(Ps[pr0 * PS_STR + kbq + tig]);
            a[1] = f2tf(Ps[(pr0 + 8) * PS_STR + kbq + tig]);
            a[2] = f2tf(Ps[pr0 * PS_STR + kbq + tig + 4]);
            a[3] = f2tf(Ps[(pr0 + 8) * PS_STR + kbq + tig + 4]);
            #pragma unroll
            for (int nt = 0; nt < 8; nt++) {
                bb[nt][0] = f2tf(Vs[(kbq + tig) * VS_STR + nt * 8 + g]);
                bb[nt][1] = f2tf(Vs[(kbq + tig + 4) * VS_STR + nt * 8 + g]);
            }
            #pragma unroll
            for (int nt = 0; nt < 8; nt++) MMA_TF32(o[nt], a, bb[nt]);
        }
    }

    // ---- write out ----
    float il0 = 1.0f / l0, il1 = 1.0f / l1;
    size_t row0 = (size_t)(b * SEQ + qb * QT + warp * 16 + g);
    #pragma unroll
    for (int nt = 0; nt < 8; nt++) {
        int col = h * HD + nt * 8 + 2 * tig;
        *(float2*)(out + row0 * D_MODEL + col) =
            make_float2(o[nt][0] * il0, o[nt][1] * il0);
        *(float2*)(out + (row0 + 8) * D_MODEL + col) =
            make_float2(o[nt][2] * il1, o[nt][3] * il1);
    }
}

// ---------------- launch ----------------
extern "C" void kernel_launch(void* const* d_in, const int* in_sizes, int n_in,
                              void* d_out, int out_size)
{
    const float* x        = (const float*)d_in[0];
    const float* ln1_w    = (const float*)d_in[1];
    const float* ln1_b    = (const float*)d_in[2];
    const float* c_attn_w = (const float*)d_in[3];
    const float* c_attn_b = (const float*)d_in[4];
    const float* c_proj_w = (const float*)d_in[5];
    const float* c_proj_b = (const float*)d_in[6];
    const float* ln2_w    = (const float*)d_in[7];
    const float* ln2_b    = (const float*)d_in[8];
    const float* fc_w     = (const float*)d_in[9];
    const float* fc_b     = (const float*)d_in[10];
    const float* proj_w   = (const float*)d_in[11];
    const float* proj_b   = (const float*)d_in[12];
    float* out = (float*)d_out;

    float *ln1, *qkv, *attn, *x1, *ln2o, *hbuf;
    cudaGetSymbolAddress((void**)&ln1,  g_ln1);
    cudaGetSymbolAddress((void**)&qkv,  g_qkv);
    cudaGetSymbolAddress((void**)&attn, g_attn);
    cudaGetSymbolAddress((void**)&x1,   g_x1);
    cudaGetSymbolAddress((void**)&ln2o, g_ln2);
    cudaGetSymbolAddress((void**)&hbuf, g_h);

    static bool attr_done = false;
    if (!attr_done) {
        cudaFuncSetAttribute(gemm_tc<0>, cudaFuncAttributeMaxDynamicSharedMemorySize, GEMM_SMEM_BYTES);
        cudaFuncSetAttribute(gemm_tc<1>, cudaFuncAttributeMaxDynamicSharedMemorySize, GEMM_SMEM_BYTES);
        cudaFuncSetAttribute(gemm_tc<2>, cudaFuncAttributeMaxDynamicSharedMemorySize, GEMM_SMEM_BYTES);
        cudaFuncSetAttribute(attn_tc,    cudaFuncAttributeMaxDynamicSharedMemorySize, ATTN_SMEM);
        attr_done = true;
    }

    ln_kernel<<<NTOK, 256>>>(x, ln1_w, ln1_b, ln1);
    gemm_tc<0><<<dim3(3 * D_MODEL / BN, NTOK / BM), 256, GEMM_SMEM_BYTES>>>(
        ln1, c_attn_w, c_attn_b, nullptr, qkv, NTOK, 3 * D_MODEL, D_MODEL);
    attn_tc<<<dim3(SEQ / QT, NHEAD, BATCH), 256, ATTN_SMEM>>>(qkv, attn);
    gemm_tc<1><<<dim3(D_MODEL / BN, NTOK / BM), 256, GEMM_SMEM_BYTES>>>(
        attn, c_proj_w, c_proj_b, x, x1, NTOK, D_MODEL, D_MODEL);
    ln_kernel<<<NTOK, 256>>>(x1, ln2_w, ln2_b, ln2o);
    gemm_tc<2><<<dim3(4 * D_MODEL / BN, NTOK / BM), 256, GEMM_SMEM_BYTES>>>(
        ln2o, fc_w, fc_b, nullptr, hbuf, NTOK, 4 * D_MODEL, D_MODEL);
    gemm_tc<1><<<dim3(D_MODEL / BN, NTOK / BM), 256, GEMM_SMEM_BYTES>>>(
        hbuf, proj_w, proj_b, x1, out, NTOK, D_MODEL, 4 * D_MODEL);
}

// round 4
// speedup vs baseline: 3.8257x; 1.0001x over previous
#include <cuda_runtime.h>
#include <math.h>
#include <stdint.h>

#define D_MODEL 1024
#define SEQ     2048
#define BATCH   2
#define NTOK    4096
#define NHEAD   16
#define HD      64

// ---------------- scratch ----------------
__device__ float g_ln1 [NTOK * D_MODEL];
__device__ float g_qkv [NTOK * 3 * D_MODEL];
__device__ float g_attn[NTOK * D_MODEL];
__device__ float g_x1  [NTOK * D_MODEL];
__device__ float g_ln2 [NTOK * D_MODEL];
__device__ float g_h   [NTOK * 4 * D_MODEL];

// ---------------- LayerNorm ----------------
__global__ __launch_bounds__(256) void ln_kernel(const float* __restrict__ x,
                                                 const float* __restrict__ w,
                                                 const float* __restrict__ b,
                                                 float* __restrict__ y)
{
    int row = blockIdx.x;
    int tid = threadIdx.x;
    const float4* xr = (const float4*)(x + (size_t)row * D_MODEL);
    float4 v = xr[tid];

    __shared__ float red[8];

    float s = v.x + v.y + v.z + v.w;
    #pragma unroll
    for (int o = 16; o > 0; o >>= 1) s += __shfl_xor_sync(0xffffffffu, s, o);
    if ((tid & 31) == 0) red[tid >> 5] = s;
    __syncthreads();
    float tot = red[0] + red[1] + red[2] + red[3] + red[4] + red[5] + red[6] + red[7];
    float mean = tot * (1.0f / 1024.0f);

    float a0 = v.x - mean, a1 = v.y - mean, a2 = v.z - mean, a3 = v.w - mean;
    __syncthreads();
    float q = a0*a0 + a1*a1 + a2*a2 + a3*a3;
    #pragma unroll
    for (int o = 16; o > 0; o >>= 1) q += __shfl_xor_sync(0xffffffffu, q, o);
    if ((tid & 31) == 0) red[tid >> 5] = q;
    __syncthreads();
    float ssq = red[0] + red[1] + red[2] + red[3] + red[4] + red[5] + red[6] + red[7];

    float sd  = sqrtf(ssq * (1.0f / 1023.0f));
    float inv = 1.0f / (sd + 1e-5f);

    float4 wv = ((const float4*)w)[tid];
    float4 bv = ((const float4*)b)[tid];
    float4 o;
    o.x = wv.x * (a0 * inv) + bv.x;
    o.y = wv.y * (a1 * inv) + bv.y;
    o.z = wv.z * (a2 * inv) + bv.z;
    o.w = wv.w * (a3 * inv) + bv.w;
    ((float4*)(y + (size_t)row * D_MODEL))[tid] = o;
}

__device__ __forceinline__ float gelu_f(float x)
{
    float x3 = x * x * x;
    return 0.5f * x * (1.0f + tanhf(0.7978845608028654f * (x + 0.044715f * x3)));
}

// raw fp32 bits as tf32 operand (HW ignores low 13 mantissa bits)
__device__ __forceinline__ uint32_t f2tf(float x) { return __float_as_uint(x); }

__device__ __forceinline__ void cp16(uint32_t dst, const void* src)
{
    asm volatile("cp.async.cg.shared.global [%0], [%1], 16;\n" :: "r"(dst), "l"(src));
}

#define MMA_TF32(c, a, b) \
    asm volatile( \
        "mma.sync.aligned.m16n8k8.row.col.f32.tf32.tf32.f32 " \
        "{%0,%1,%2,%3}, {%4,%5,%6,%7}, {%8,%9}, {%0,%1,%2,%3};\n" \
        : "+f"((c)[0]), "+f"((c)[1]), "+f"((c)[2]), "+f"((c)[3]) \
        : "r"((a)[0]), "r"((a)[1]), "r"((a)[2]), "r"((a)[3]), \
          "r"((b)[0]), "r"((b)[1]))

// ---------------- tf32 GEMM 128x128x32 ----------------
#define BM 128
#define BN 128
#define BKT 32
#define AS_STRIDE 36
#define BS_STRIDE 136
#define AS_FLOATS (BM * AS_STRIDE)
#define BS_FLOATS (BKT * BS_STRIDE)
#define STAGE_FLOATS (AS_FLOATS + BS_FLOATS)
#define GEMM_SMEM_BYTES (2 * STAGE_FLOATS * 4)

template<int MODE>
__global__ __launch_bounds__(256, 2) void gemm_tc(const float* __restrict__ A,
                                                  const float* __restrict__ Bm,
                                                  const float* __restrict__ bias,
                                                  const float* __restrict__ res,
                                                  float* __restrict__ C,
                                                  int M, int N, int K)
{
    extern __shared__ float sm[];
    int tid  = threadIdx.x;
    int bx = blockIdx.x, by = blockIdx.y;
    int warp = tid >> 5, lane = tid & 31;
    int wm = warp >> 2, wn = warp & 3;
    int g = lane >> 2, tig = lane & 3;

    const float* Ablk = A + (size_t)(by * BM) * K;
    const float* Bblk = Bm + bx * BN;

    float c[4][4][4];
    #pragma unroll
    for (int mt = 0; mt < 4; mt++)
        #pragma unroll
        for (int nt = 0; nt < 4; nt++)
            #pragma unroll
            for (int r = 0; r < 4; r++) c[mt][nt][r] = 0.0f;

    const int iters = K / BKT;
    uint32_t smem_base = (uint32_t)__cvta_generic_to_shared(sm);

    auto load_stage = [&](int it, int buf) {
        uint32_t as = smem_base + (uint32_t)(buf * STAGE_FLOATS) * 4u;
        uint32_t bs = as + (uint32_t)AS_FLOATS * 4u;
        int k0 = it * BKT;
        #pragma unroll
        for (int i = 0; i < 4; i++) {
            int q = tid + 256 * i;
            int ar = q >> 3, ac = (q & 7) * 4;
            cp16(as + (uint32_t)(ar * AS_STRIDE + ac) * 4u,
                 Ablk + (size_t)ar * K + k0 + ac);
            int br = q >> 5, bc = (q & 31) * 4;
            cp16(bs + (uint32_t)(br * BS_STRIDE + bc) * 4u,
                 Bblk + (size_t)(k0 + br) * N + bc);
        }
        asm volatile("cp.async.commit_group;\n" ::: "memory");
    };

    load_stage(0, 0);

    for (int it = 0; it < iters; it++) {
        if (it + 1 < iters) {
            load_stage(it + 1, (it + 1) & 1);
            asm volatile("cp.async.wait_group 1;\n" ::: "memory");
        } else {
            asm volatile("cp.async.wait_group 0;\n" ::: "memory");
        }
        __syncthreads();

        const float* As = sm + (it & 1) * STAGE_FLOATS;
        const float* Bs = As + AS_FLOATS;

        #pragma unroll
        for (int kk = 0; kk < 4; kk++) {
            int kb = kk * 8;
            uint32_t a[4][4], b[4][2];
            #pragma unroll
            for (int mt = 0; mt < 4; mt++) {
                int m = wm * 64 + mt * 16 + g;
                a[mt][0] = f2tf(As[m * AS_STRIDE + kb + tig]);
                a[mt][1] = f2tf(As[(m + 8) * AS_STRIDE + kb + tig]);
                a[mt][2] = f2tf(As[m * AS_STRIDE + kb + tig + 4]);
                a[mt][3] = f2tf(As[(m + 8) * AS_STRIDE + kb + tig + 4]);
            }
            #pragma unroll
            for (int nt = 0; nt < 4; nt++) {
                int n = wn * 32 + nt * 8 + g;
                b[nt][0] = f2tf(Bs[(kb + tig) * BS_STRIDE + n]);
                b[nt][1] = f2tf(Bs[(kb + tig + 4) * BS_STRIDE + n]);
            }
            #pragma unroll
            for (int mt = 0; mt < 4; mt++)
                #pragma unroll
                for (int nt = 0; nt < 4; nt++)
                    MMA_TF32(c[mt][nt], a[mt], b[nt]);
        }
        __syncthreads();
    }

    #pragma unroll
    for (int mt = 0; mt < 4; mt++) {
        int row0 = by * BM + wm * 64 + mt * 16 + g;
        #pragma unroll
        for (int nt = 0; nt < 4; nt++) {
            int col = bx * BN + wn * 32 + nt * 8 + tig * 2;
            float b0 = __ldg(bias + col), b1 = __ldg(bias + col + 1);
            float v0 = c[mt][nt][0] + b0, v1 = c[mt][nt][1] + b1;
            float v2 = c[mt][nt][2] + b0, v3 = c[mt][nt][3] + b1;
            if (MODE == 1) {
                const float* r0 = res + (size_t)row0 * N + col;
                const float* r1 = res + (size_t)(row0 + 8) * N + col;
                v0 += r0[0]; v1 += r0[1];
                v2 += r1[0]; v3 += r1[1];
            }
            if (MODE == 2) {
                v0 = gelu_f(v0); v1 = gelu_f(v1);
                v2 = gelu_f(v2); v3 = gelu_f(v3);
            }
            *(float2*)(C + (size_t)row0 * N + col)       = make_float2(v0, v1);
            *(float2*)(C + (size_t)(row0 + 8) * N + col) = make_float2(v2, v3);
        }
    }
}

// ---------------- tensor-core flash attention ----------------
// 128 q-rows per block, 64-key tiles, 8 warps (each warp: 16 q-rows x all 64 cols).
// Layouts (floats): Qs[128][QS_STR], Ks[64][KS_STR], Vs[64][VS_STR], Ps[128][PS_STR]
// Strides chosen so all fragment LDS are bank-conflict-free:
//   A-pattern (stride%32==4): bank = 4*g + tig ; B-K pattern (stride%32==4): 4g+tig
//   B-V pattern (stride%32==8): bank = 8*tig + g
#define QT 128
#define KT 64
#define QS_STR 68
#define KS_STR 68
#define VS_STR 72
#define PS_STR 68
#define ATTN_SMEM ((QT*QS_STR + KT*KS_STR + KT*VS_STR + QT*PS_STR) * 4)

__global__ __launch_bounds__(256, 2) void attn_tc(const float* __restrict__ qkv,
                                                  float* __restrict__ out)
{
    extern __shared__ float sm[];
    float* Qs = sm;
    float* Ks = Qs + QT * QS_STR;
    float* Vs = Ks + KT * KS_STR;
    float* Ps = Vs + KT * VS_STR;

    int tid = threadIdx.x, warp = tid >> 5, lane = tid & 31;
    int g = lane >> 2, tig = lane & 3;
    int qb = blockIdx.x, h = blockIdx.y, b = blockIdx.z;

    const float* base = qkv + (size_t)b * SEQ * (3 * D_MODEL) + h * HD;

    uint32_t qs_u = (uint32_t)__cvta_generic_to_shared(Qs);
    uint32_t ks_u = (uint32_t)__cvta_generic_to_shared(Ks);
    uint32_t vs_u = (uint32_t)__cvta_generic_to_shared(Vs);

    // Q tile: 128 x 64
    #pragma unroll
    for (int i = 0; i < 8; i++) {
        int idx = i * 256 + tid;
        int r = idx >> 4, d4 = (idx & 15) * 4;
        cp16(qs_u + (uint32_t)(r * QS_STR + d4) * 4u,
             base + (size_t)(qb * QT + r) * (3 * D_MODEL) + d4);
    }
    asm volatile("cp.async.commit_group;\n" ::: "memory");

    float o[8][4];
    #pragma unroll
    for (int nt = 0; nt < 8; nt++)
        #pragma unroll
        for (int r = 0; r < 4; r++) o[nt][r] = 0.0f;
    float m0 = -INFINITY, m1 = -INFINITY, l0 = 0.0f, l1 = 0.0f;

    int qrow_lo = qb * QT + warp * 16;      // warp's first q row
    int kb_end = 2 * qb + 1;

    for (int kb = 0; kb <= kb_end; kb++) {
        __syncthreads();   // everyone done with previous K/V
        #pragma unroll
        for (int i = 0; i < 4; i++) {
            int idx = i * 256 + tid;
            int r = idx >> 4, d4 = (idx & 15) * 4;
            const float* krow = base + D_MODEL + (size_t)(kb * KT + r) * (3 * D_MODEL) + d4;
            cp16(ks_u + (uint32_t)(r * KS_STR + d4) * 4u, krow);
            cp16(vs_u + (uint32_t)(r * VS_STR + d4) * 4u, krow + D_MODEL);
        }
        asm volatile("cp.async.commit_group;\n" ::: "memory");
        asm volatile("cp.async.wait_group 0;\n" ::: "memory");
        __syncthreads();

        if (kb * 64 > qrow_lo - qb * QT + qb * QT + 15 + warp * 0 &&
            kb * 64 > qb * QT + warp * 16 + 15) { continue; }  // fully masked for warp

        // ---- S = Q K^T ----
        float s[8][4];
        #pragma unroll
        for (int nt = 0; nt < 8; nt++)
            #pragma unroll
            for (int r = 0; r < 4; r++) s[nt][r] = 0.0f;

        #pragma unroll
        for (int ks = 0; ks < 8; ks++) {
            int kbq = ks * 8;
            uint32_t a[4], bb[8][2];
            int mrow = warp * 16 + g;
            a[0] = f2tf(Qs[mrow * QS_STR + kbq + tig]);
            a[1] = f2tf(Qs[(mrow + 8) * QS_STR + kbq + tig]);
            a[2] = f2tf(Qs[mrow * QS_STR + kbq + tig + 4]);
            a[3] = f2tf(Qs[(mrow + 8) * QS_STR + kbq + tig + 4]);
            #pragma unroll
            for (int nt = 0; nt < 8; nt++) {
                bb[nt][0] = f2tf(Ks[(nt * 8 + g) * KS_STR + kbq + tig]);
                bb[nt][1] = f2tf(Ks[(nt * 8 + g) * KS_STR + kbq + tig + 4]);
            }
            #pragma unroll
            for (int nt = 0; nt < 8; nt++) MMA_TF32(s[nt], a, bb[nt]);
        }

        // ---- scale + causal mask ----
        const float scale = 0.125f;
        int q0 = qb * QT + warp * 16 + g;
        int q1 = q0 + 8;
        bool diag = (kb * 64 + 63 > qrow_lo);   // tile may cross diagonal for this warp
        #pragma unroll
        for (int nt = 0; nt < 8; nt++) {
            int key = kb * 64 + nt * 8 + 2 * tig;
            s[nt][0] *= scale; s[nt][1] *= scale;
            s[nt][2] *= scale; s[nt][3] *= scale;
            if (diag) {
                if (key     > q0) s[nt][0] = -1e30f;
                if (key + 1 > q0) s[nt][1] = -1e30f;
                if (key     > q1) s[nt][2] = -1e30f;
                if (key + 1 > q1) s[nt][3] = -1e30f;
            }
        }

        // ---- online softmax (rows q0, q1 owned by this warp) ----
        float rmax0 = -INFINITY, rmax1 = -INFINITY;
        #pragma unroll
        for (int nt = 0; nt < 8; nt++) {
            rmax0 = fmaxf(rmax0, fmaxf(s[nt][0], s[nt][1]));
            rmax1 = fmaxf(rmax1, fmaxf(s[nt][2], s[nt][3]));
        }
        rmax0 = fmaxf(rmax0, __shfl_xor_sync(0xffffffffu, rmax0, 1));
        rmax0 = fmaxf(rmax0, __shfl_xor_sync(0xffffffffu, rmax0, 2));
        rmax1 = fmaxf(rmax1, __shfl_xor_sync(0xffffffffu, rmax1, 1));
        rmax1 = fmaxf(rmax1, __shfl_xor_sync(0xffffffffu, rmax1, 2));

        float mn0 = fmaxf(m0, rmax0), mn1 = fmaxf(m1, rmax1);
        float corr0 = __expf(m0 - mn0), corr1 = __expf(m1 - mn1);

        float rs0 = 0.0f, rs1 = 0.0f;
        #pragma unroll
        for (int nt = 0; nt < 8; nt++) {
            s[nt][0] = __expf(s[nt][0] - mn0);
            s[nt][1] = __expf(s[nt][1] - mn0);
            s[nt][2] = __expf(s[nt][2] - mn1);
            s[nt][3] = __expf(s[nt][3] - mn1);
            rs0 += s[nt][0] + s[nt][1];
            rs1 += s[nt][2] + s[nt][3];
        }
        rs0 += __shfl_xor_sync(0xffffffffu, rs0, 1);
        rs0 += __shfl_xor_sync(0xffffffffu, rs0, 2);
        rs1 += __shfl_xor_sync(0xffffffffu, rs1, 1);
        rs1 += __shfl_xor_sync(0xffffffffu, rs1, 2);

        l0 = l0 * corr0 + rs0;  m0 = mn0;
        l1 = l1 * corr1 + rs1;  m1 = mn1;

        // ---- P to (warp-private) smem ----
        int pr0 = warp * 16 + g;
        #pragma unroll
        for (int nt = 0; nt < 8; nt++) {
            *(float2*)&Ps[pr0 * PS_STR + nt * 8 + 2 * tig]       = make_float2(s[nt][0], s[nt][1]);
            *(float2*)&Ps[(pr0 + 8) * PS_STR + nt * 8 + 2 * tig] = make_float2(s[nt][2], s[nt][3]);
        }
        __syncwarp();

        // rescale O
        #pragma unroll
        for (int nt = 0; nt < 8; nt++) {
            o[nt][0] *= corr0; o[nt][1] *= corr0;
            o[nt][2] *= corr1; o[nt][3] *= corr1;
        }

        // ---- O += P V ----
        #pragma unroll
        for (int ks = 0; ks < 8; ks++) {
            int kbq = ks * 8;
            uint32_t a[4], bb[8][2];
            a[0] = f2tf(Ps[pr0 * PS_STR + kbq + tig]);
            a[1] = f2tf(Ps[(pr0 + 8) * PS_STR + kbq + tig]);
            a[2] = f2tf(Ps[pr0 * PS_STR + kbq + tig + 4]);
            a[3] = f2tf(Ps[(pr0 + 8) * PS_STR + kbq + tig + 4]);
            #pragma unroll
            for (int nt = 0; nt < 8; nt++) {
                bb[nt][0] = f2tf(Vs[(kbq + tig) * VS_STR + nt * 8 + g]);
                bb[nt][1] = f2tf(Vs[(kbq + tig + 4) * VS_STR + nt * 8 + g]);
            }
            #pragma unroll
            for (int nt = 0; nt < 8; nt++) MMA_TF32(o[nt], a, bb[nt]);
        }
    }

    // ---- write out ----
    float il0 = 1.0f / l0, il1 = 1.0f / l1;
    size_t row0 = (size_t)(b * SEQ + qb * QT + warp * 16 + g);
    #pragma unroll
    for (int nt = 0; nt < 8; nt++) {
        int col = h * HD + nt * 8 + 2 * tig;
        *(float2*)(out + row0 * D_MODEL + col) =
            make_float2(o[nt][0] * il0, o[nt][1] * il0);
        *(float2*)(out + (row0 + 8) * D_MODEL + col) =
            make_float2(o[nt][2] * il1, o[nt][3] * il1);
    }
}

// ---------------- launch ----------------
extern "C" void kernel_launch(void* const* d_in, const int* in_sizes, int n_in,
                              void* d_out, int out_size)
{
    const float* x        = (const float*)d_in[0];
    const float* ln1_w    = (const float*)d_in[1];
    const float* ln1_b    = (const float*)d_in[2];
    const float* c_attn_w = (const float*)d_in[3];
    const float* c_attn_b = (const float*)d_in[4];
    const float* c_proj_w = (const float*)d_in[5];
    const float* c_proj_b = (const float*)d_in[6];
    const float* ln2_w    = (const float*)d_in[7];
    const float* ln2_b    = (const float*)d_in[8];
    const float* fc_w     = (const float*)d_in[9];
    const float* fc_b     = (const float*)d_in[10];
    const float* proj_w   = (const float*)d_in[11];
    const float* proj_b   = (const float*)d_in[12];
    float* out = (float*)d_out;

    float *ln1, *qkv, *attn, *x1, *ln2o, *hbuf;
    cudaGetSymbolAddress((void**)&ln1,  g_ln1);
    cudaGetSymbolAddress((void**)&qkv,  g_qkv);
    cudaGetSymbolAddress((void**)&attn, g_attn);
    cudaGetSymbolAddress((void**)&x1,   g_x1);
    cudaGetSymbolAddress((void**)&ln2o, g_ln2);
    cudaGetSymbolAddress((void**)&hbuf, g_h);

    static bool attr_done = false;
    if (!attr_done) {
        cudaFuncSetAttribute(gemm_tc<0>, cudaFuncAttributeMaxDynamicSharedMemorySize, GEMM_SMEM_BYTES);
        cudaFuncSetAttribute(gemm_tc<1>, cudaFuncAttributeMaxDynamicSharedMemorySize, GEMM_SMEM_BYTES);
        cudaFuncSetAttribute(gemm_tc<2>, cudaFuncAttributeMaxDynamicSharedMemorySize, GEMM_SMEM_BYTES);
        cudaFuncSetAttribute(attn_tc,    cudaFuncAttributeMaxDynamicSharedMemorySize, ATTN_SMEM);
        attr_done = true;
    }

    ln_kernel<<<NTOK, 256>>>(x, ln1_w, ln1_b, ln1);
    gemm_tc<0><<<dim3(3 * D_MODEL / BN, NTOK / BM), 256, GEMM_SMEM_BYTES>>>(
        ln1, c_attn_w, c_attn_b, nullptr, qkv, NTOK, 3 * D_MODEL, D_MODEL);
    attn_tc<<<dim3(SEQ / QT, NHEAD, BATCH), 256, ATTN_SMEM>>>(qkv, attn);
    gemm_tc<1><<<dim3(D_MODEL / BN, NTOK / BM), 256, GEMM_SMEM_BYTES>>>(
        attn, c_proj_w, c_proj_b, x, x1, NTOK, D_MODEL, D_MODEL);
    ln_kernel<<<NTOK, 256>>>(x1, ln2_w, ln2_b, ln2o);
    gemm_tc<2><<<dim3(4 * D_MODEL / BN, NTOK / BM), 256, GEMM_SMEM_BYTES>>>(
        ln2o, fc_w, fc_b, nullptr, hbuf, NTOK, 4 * D_MODEL, D_MODEL);
    gemm_tc<1><<<dim3(D_MODEL / BN, NTOK / BM), 256, GEMM_SMEM_BYTES>>>(
        hbuf, proj_w, proj_b, x1, out, NTOK, D_MODEL, 4 * D_MODEL);
}

// round 5
// speedup vs baseline: 3.8261x; 1.0001x over previous
#include <cuda_runtime.h>
#include <math.h>
#include <stdint.h>

#define D_MODEL 1024
#define SEQ     2048
#define BATCH   2
#define NTOK    4096
#define NHEAD   16
#define HD      64

// ---------------- scratch ----------------
__device__ float g_ln1 [NTOK * D_MODEL];
__device__ float g_qkv [NTOK * 3 * D_MODEL];
__device__ float g_attn[NTOK * D_MODEL];
__device__ float g_x1  [NTOK * D_MODEL];
__device__ float g_ln2 [NTOK * D_MODEL];
__device__ float g_h   [NTOK * 4 * D_MODEL];

// raw fp32 bits as tf32 operand (HW ignores low 13 mantissa bits)
__device__ __forceinline__ uint32_t f2tf(float x) { return __float_as_uint(x); }

// round-to-nearest tf32, returned as float (low 13 bits zero)
__device__ __forceinline__ float rntf(float x)
{
    uint32_t r;
    asm("cvt.rna.tf32.f32 %0, %1;\n" : "=r"(r) : "f"(x));
    return __uint_as_float(r);
}

// ---------------- LayerNorm (output rounded to tf32 grid) ----------------
__global__ __launch_bounds__(256) void ln_kernel(const float* __restrict__ x,
                                                 const float* __restrict__ w,
                                                 const float* __restrict__ b,
                                                 float* __restrict__ y)
{
    int row = blockIdx.x;
    int tid = threadIdx.x;
    const float4* xr = (const float4*)(x + (size_t)row * D_MODEL);
    float4 v = xr[tid];

    __shared__ float red[8];

    float s = v.x + v.y + v.z + v.w;
    #pragma unroll
    for (int o = 16; o > 0; o >>= 1) s += __shfl_xor_sync(0xffffffffu, s, o);
    if ((tid & 31) == 0) red[tid >> 5] = s;
    __syncthreads();
    float tot = red[0] + red[1] + red[2] + red[3] + red[4] + red[5] + red[6] + red[7];
    float mean = tot * (1.0f / 1024.0f);

    float a0 = v.x - mean, a1 = v.y - mean, a2 = v.z - mean, a3 = v.w - mean;
    __syncthreads();
    float q = a0*a0 + a1*a1 + a2*a2 + a3*a3;
    #pragma unroll
    for (int o = 16; o > 0; o >>= 1) q += __shfl_xor_sync(0xffffffffu, q, o);
    if ((tid & 31) == 0) red[tid >> 5] = q;
    __syncthreads();
    float ssq = red[0] + red[1] + red[2] + red[3] + red[4] + red[5] + red[6] + red[7];

    float sd  = sqrtf(ssq * (1.0f / 1023.0f));
    float inv = 1.0f / (sd + 1e-5f);

    float4 wv = ((const float4*)w)[tid];
    float4 bv = ((const float4*)b)[tid];
    float4 o;
    o.x = rntf(wv.x * (a0 * inv) + bv.x);
    o.y = rntf(wv.y * (a1 * inv) + bv.y);
    o.z = rntf(wv.z * (a2 * inv) + bv.z);
    o.w = rntf(wv.w * (a3 * inv) + bv.w);
    ((float4*)(y + (size_t)row * D_MODEL))[tid] = o;
}

__device__ __forceinline__ float gelu_f(float x)
{
    float x3 = x * x * x;
    return 0.5f * x * (1.0f + tanhf(0.7978845608028654f * (x + 0.044715f * x3)));
}

__device__ __forceinline__ void cp16(uint32_t dst, const void* src)
{
    asm volatile("cp.async.cg.shared.global [%0], [%1], 16;\n" :: "r"(dst), "l"(src));
}

#define MMA_TF32(c, a, b) \
    asm volatile( \
        "mma.sync.aligned.m16n8k8.row.col.f32.tf32.tf32.f32 " \
        "{%0,%1,%2,%3}, {%4,%5,%6,%7}, {%8,%9}, {%0,%1,%2,%3};\n" \
        : "+f"((c)[0]), "+f"((c)[1]), "+f"((c)[2]), "+f"((c)[3]) \
        : "r"((a)[0]), "r"((a)[1]), "r"((a)[2]), "r"((a)[3]), \
          "r"((b)[0]), "r"((b)[1]))

// ---------------- tf32 GEMM 128x128x32, single-barrier mainloop ----------------
#define BM 128
#define BN 128
#define BKT 32
#define AS_STRIDE 36
#define BS_STRIDE 136
#define AS_FLOATS (BM * AS_STRIDE)
#define BS_FLOATS (BKT * BS_STRIDE)
#define STAGE_FLOATS (AS_FLOATS + BS_FLOATS)
#define GEMM_SMEM_BYTES (2 * STAGE_FLOATS * 4)

// MODE 0: C = round(A@B + bias) ; MODE 1: C = res + A@B + bias (fp32)
// MODE 2: C = round(gelu(A@B + bias))
template<int MODE>
__global__ __launch_bounds__(256, 2) void gemm_tc(const float* __restrict__ A,
                                                  const float* __restrict__ Bm,
                                                  const float* __restrict__ bias,
                                                  const float* __restrict__ res,
                                                  float* __restrict__ C,
                                                  int M, int N, int K)
{
    extern __shared__ float sm[];
    int tid  = threadIdx.x;
    int bx = blockIdx.x, by = blockIdx.y;
    int warp = tid >> 5, lane = tid & 31;
    int wm = warp >> 2, wn = warp & 3;
    int g = lane >> 2, tig = lane & 3;

    const float* Ablk = A + (size_t)(by * BM) * K;
    const float* Bblk = Bm + bx * BN;

    float c[4][4][4];
    #pragma unroll
    for (int mt = 0; mt < 4; mt++)
        #pragma unroll
        for (int nt = 0; nt < 4; nt++)
            #pragma unroll
            for (int r = 0; r < 4; r++) c[mt][nt][r] = 0.0f;

    const int iters = K / BKT;
    uint32_t smem_base = (uint32_t)__cvta_generic_to_shared(sm);

    auto load_stage = [&](int it, int buf) {
        uint32_t as = smem_base + (uint32_t)(buf * STAGE_FLOATS) * 4u;
        uint32_t bs = as + (uint32_t)AS_FLOATS * 4u;
        int k0 = it * BKT;
        #pragma unroll
        for (int i = 0; i < 4; i++) {
            int q = tid + 256 * i;
            int ar = q >> 3, ac = (q & 7) * 4;
            cp16(as + (uint32_t)(ar * AS_STRIDE + ac) * 4u,
                 Ablk + (size_t)ar * K + k0 + ac);
            int br = q >> 5, bc = (q & 31) * 4;
            cp16(bs + (uint32_t)(br * BS_STRIDE + bc) * 4u,
                 Bblk + (size_t)(k0 + br) * N + bc);
        }
        asm volatile("cp.async.commit_group;\n" ::: "memory");
    };

    load_stage(0, 0);

    for (int it = 0; it < iters; it++) {
        // all outstanding loads (stage it) complete
        asm volatile("cp.async.wait_group 0;\n" ::: "memory");
        __syncthreads();   // every warp done computing it-1, stage it visible
        if (it + 1 < iters) load_stage(it + 1, (it + 1) & 1);   // overlaps compute(it)

        const float* As = sm + (it & 1) * STAGE_FLOATS;
        const float* Bs = As + AS_FLOATS;

        #pragma unroll
        for (int kk = 0; kk < 4; kk++) {
            int kb = kk * 8;
            uint32_t a[4][4], b[4][2];
            #pragma unroll
            for (int mt = 0; mt < 4; mt++) {
                int m = wm * 64 + mt * 16 + g;
                a[mt][0] = f2tf(As[m * AS_STRIDE + kb + tig]);
                a[mt][1] = f2tf(As[(m + 8) * AS_STRIDE + kb + tig]);
                a[mt][2] = f2tf(As[m * AS_STRIDE + kb + tig + 4]);
                a[mt][3] = f2tf(As[(m + 8) * AS_STRIDE + kb + tig + 4]);
            }
            #pragma unroll
            for (int nt = 0; nt < 4; nt++) {
                int n = wn * 32 + nt * 8 + g;
                b[nt][0] = f2tf(Bs[(kb + tig) * BS_STRIDE + n]);
                b[nt][1] = f2tf(Bs[(kb + tig + 4) * BS_STRIDE + n]);
            }
            #pragma unroll
            for (int mt = 0; mt < 4; mt++)
                #pragma unroll
                for (int nt = 0; nt < 4; nt++)
                    MMA_TF32(c[mt][nt], a[mt], b[nt]);
        }
    }

    #pragma unroll
    for (int mt = 0; mt < 4; mt++) {
        int row0 = by * BM + wm * 64 + mt * 16 + g;
        #pragma unroll
        for (int nt = 0; nt < 4; nt++) {
            int col = bx * BN + wn * 32 + nt * 8 + tig * 2;
            float b0 = __ldg(bias + col), b1 = __ldg(bias + col + 1);
            float v0 = c[mt][nt][0] + b0, v1 = c[mt][nt][1] + b1;
            float v2 = c[mt][nt][2] + b0, v3 = c[mt][nt][3] + b1;
            if (MODE == 1) {
                const float* r0 = res + (size_t)row0 * N + col;
                const float* r1 = res + (size_t)(row0 + 8) * N + col;
                v0 += r0[0]; v1 += r0[1];
                v2 += r1[0]; v3 += r1[1];
            }
            if (MODE == 2) {
                v0 = gelu_f(v0); v1 = gelu_f(v1);
                v2 = gelu_f(v2); v3 = gelu_f(v3);
            }
            if (MODE == 0 || MODE == 2) {   // consumed as MMA operand downstream
                v0 = rntf(v0); v1 = rntf(v1);
                v2 = rntf(v2); v3 = rntf(v3);
            }
            *(float2*)(C + (size_t)row0 * N + col)       = make_float2(v0, v1);
            *(float2*)(C + (size_t)(row0 + 8) * N + col) = make_float2(v2, v3);
        }
    }
}

// ---------------- tensor-core flash attention ----------------
#define QT 128
#define KT 64
#define QS_STR 68
#define KS_STR 68
#define VS_STR 72
#define PS_STR 68
#define ATTN_SMEM ((QT*QS_STR + KT*KS_STR + KT*VS_STR + QT*PS_STR) * 4)

__global__ __launch_bounds__(256, 2) void attn_tc(const float* __restrict__ qkv,
                                                  float* __restrict__ out)
{
    extern __shared__ float sm[];
    float* Qs = sm;
    float* Ks = Qs + QT * QS_STR;
    float* Vs = Ks + KT * KS_STR;
    float* Ps = Vs + KT * VS_STR;

    int tid = threadIdx.x, warp = tid >> 5, lane = tid & 31;
    int g = lane >> 2, tig = lane & 3;
    // heavy blocks (large qb) first -> better wave packing
    int qb = gridDim.x - 1 - blockIdx.x;
    int h = blockIdx.y, b = blockIdx.z;

    const float* base = qkv + (size_t)b * SEQ * (3 * D_MODEL) + h * HD;

    uint32_t qs_u = (uint32_t)__cvta_generic_to_shared(Qs);
    uint32_t ks_u = (uint32_t)__cvta_generic_to_shared(Ks);
    uint32_t vs_u = (uint32_t)__cvta_generic_to_shared(Vs);

    #pragma unroll
    for (int i = 0; i < 8; i++) {
        int idx = i * 256 + tid;
        int r = idx >> 4, d4 = (idx & 15) * 4;
        cp16(qs_u + (uint32_t)(r * QS_STR + d4) * 4u,
             base + (size_t)(qb * QT + r) * (3 * D_MODEL) + d4);
    }
    asm volatile("cp.async.commit_group;\n" ::: "memory");

    float o[8][4];
    #pragma unroll
    for (int nt = 0; nt < 8; nt++)
        #pragma unroll
        for (int r = 0; r < 4; r++) o[nt][r] = 0.0f;
    float m0 = -INFINITY, m1 = -INFINITY, l0 = 0.0f, l1 = 0.0f;

    int qrow_lo = qb * QT + warp * 16;
    int kb_end = 2 * qb + 1;

    for (int kb = 0; kb <= kb_end; kb++) {
        __syncthreads();
        #pragma unroll
        for (int i = 0; i < 4; i++) {
            int idx = i * 256 + tid;
            int r = idx >> 4, d4 = (idx & 15) * 4;
            const float* krow = base + D_MODEL + (size_t)(kb * KT + r) * (3 * D_MODEL) + d4;
            cp16(ks_u + (uint32_t)(r * KS_STR + d4) * 4u, krow);
            cp16(vs_u + (uint32_t)(r * VS_STR + d4) * 4u, krow + D_MODEL);
        }
        asm volatile("cp.async.commit_group;\n" ::: "memory");
        asm volatile("cp.async.wait_group 0;\n" ::: "memory");
        __syncthreads();

        if (kb * 64 > qrow_lo + 15) continue;   // tile fully masked for this warp

        // ---- S = Q K^T ----
        float s[8][4];
        #pragma unroll
        for (int nt = 0; nt < 8; nt++)
            #pragma unroll
            for (int r = 0; r < 4; r++) s[nt][r] = 0.0f;

        #pragma unroll
        for (int ks = 0; ks < 8; ks++) {
            int kbq = ks * 8;
            uint32_t a[4], bb[8][2];
            int mrow = warp * 16 + g;
            a[0] = f2tf(Qs[mrow * QS_STR + kbq + tig]);
            a[1] = f2tf(Qs[(mrow + 8) * QS_STR + kbq + tig]);
            a[2] = f2tf(Qs[mrow * QS_STR + kbq + tig + 4]);
            a[3] = f2tf(Qs[(mrow + 8) * QS_STR + kbq + tig + 4]);
            #pragma unroll
            for (int nt = 0; nt < 8; nt++) {
                bb[nt][0] = f2tf(Ks[(nt * 8 + g) * KS_STR + kbq + tig]);
                bb[nt][1] = f2tf(Ks[(nt * 8 + g) * KS_STR + kbq + tig + 4]);
            }
            #pragma unroll
            for (int nt = 0; nt < 8; nt++) MMA_TF32(s[nt], a, bb[nt]);
        }

        const float scale = 0.125f;
        int q0 = qb * QT + warp * 16 + g;
        int q1 = q0 + 8;
        bool diag = (kb * 64 + 63 > qrow_lo);
        #pragma unroll
        for (int nt = 0; nt < 8; nt++) {
            int key = kb * 64 + nt * 8 + 2 * tig;
            s[nt][0] *= scale; s[nt][1] *= scale;
            s[nt][2] *= scale; s[nt][3] *= scale;
            if (diag) {
                if (key     > q0) s[nt][0] = -1e30f;
                if (key + 1 > q0) s[nt][1] = -1e30f;
                if (key     > q1) s[nt][2] = -1e30f;
                if (key + 1 > q1) s[nt][3] = -1e30f;
            }
        }

        float rmax0 = -INFINITY, rmax1 = -INFINITY;
        #pragma unroll
        for (int nt = 0; nt < 8; nt++) {
            rmax0 = fmaxf(rmax0, fmaxf(s[nt][0], s[nt][1]));
            rmax1 = fmaxf(rmax1, fmaxf(s[nt][2], s[nt][3]));
        }
        rmax0 = fmaxf(rmax0, __shfl_xor_sync(0xffffffffu, rmax0, 1));
        rmax0 = fmaxf(rmax0, __shfl_xor_sync(0xffffffffu, rmax0, 2));
        rmax1 = fmaxf(rmax1, __shfl_xor_sync(0xffffffffu, rmax1, 1));
        rmax1 = fmaxf(rmax1, __shfl_xor_sync(0xffffffffu, rmax1, 2));

        float mn0 = fmaxf(m0, rmax0), mn1 = fmaxf(m1, rmax1);
        float corr0 = __expf(m0 - mn0), corr1 = __expf(m1 - mn1);

        float rs0 = 0.0f, rs1 = 0.0f;
        #pragma unroll
        for (int nt = 0; nt < 8; nt++) {
            s[nt][0] = __expf(s[nt][0] - mn0);
            s[nt][1] = __expf(s[nt][1] - mn0);
            s[nt][2] = __expf(s[nt][2] - mn1);
            s[nt][3] = __expf(s[nt][3] - mn1);
            rs0 += s[nt][0] + s[nt][1];
            rs1 += s[nt][2] + s[nt][3];
        }
        rs0 += __shfl_xor_sync(0xffffffffu, rs0, 1);
        rs0 += __shfl_xor_sync(0xffffffffu, rs0, 2);
        rs1 += __shfl_xor_sync(0xffffffffu, rs1, 1);
        rs1 += __shfl_xor_sync(0xffffffffu, rs1, 2);

        l0 = l0 * corr0 + rs0;  m0 = mn0;
        l1 = l1 * corr1 + rs1;  m1 = mn1;

        int pr0 = warp * 16 + g;
        #pragma unroll
        for (int nt = 0; nt < 8; nt++) {
            *(float2*)&Ps[pr0 * PS_STR + nt * 8 + 2 * tig]       = make_float2(s[nt][0], s[nt][1]);
            *(float2*)&Ps[(pr0 + 8) * PS_STR + nt * 8 + 2 * tig] = make_float2(s[nt][2], s[nt][3]);
        }
        __syncwarp();

        #pragma unroll
        for (int nt = 0; nt < 8; nt++) {
            o[nt][0] *= corr0; o[nt][1] *= corr0;
            o[nt][2] *= corr1; o[nt][3] *= corr1;
        }

        #pragma unroll
        for (int ks = 0; ks < 8; ks++) {
            int kbq = ks * 8;
            uint32_t a[4], bb[8][2];
            a[0] = f2tf(Ps[pr0 * PS_STR + kbq + tig]);
            a[1] = f2tf(Ps[(pr0 + 8) * PS_STR + kbq + tig]);
            a[2] = f2tf(Ps[pr0 * PS_STR + kbq + tig + 4]);
            a[3] = f2tf(Ps[(pr0 + 8) * PS_STR + kbq + tig + 4]);
            #pragma unroll
            for (int nt = 0; nt < 8; nt++) {
                bb[nt][0] = f2tf(Vs[(kbq + tig) * VS_STR + nt * 8 + g]);
                bb[nt][1] = f2tf(Vs[(kbq + tig + 4) * VS_STR + nt * 8 + g]);
            }
            #pragma unroll
            for (int nt = 0; nt < 8; nt++) MMA_TF32(o[nt], a, bb[nt]);
        }
    }

    float il0 = 1.0f / l0, il1 = 1.0f / l1;
    size_t row0 = (size_t)(b * SEQ + qb * QT + warp * 16 + g);
    #pragma unroll
    for (int nt = 0; nt < 8; nt++) {
        int col = h * HD + nt * 8 + 2 * tig;
        *(float2*)(out + row0 * D_MODEL + col) =
            make_float2(rntf(o[nt][0] * il0), rntf(o[nt][1] * il0));
        *(float2*)(out + (row0 + 8) * D_MODEL + col) =
            make_float2(rntf(o[nt][2] * il1), rntf(o[nt][3] * il1));
    }
}

// ---------------- launch ----------------
extern "C" void kernel_launch(void* const* d_in, const int* in_sizes, int n_in,
                              void* d_out, int out_size)
{
    const float* x        = (const float*)d_in[0];
    const float* ln1_w    = (const float*)d_in[1];
    const float* ln1_b    = (const float*)d_in[2];
    const float* c_attn_w = (const float*)d_in[3];
    const float* c_attn_b = (const float*)d_in[4];
    const float* c_proj_w = (const float*)d_in[5];
    const float* c_proj_b = (const float*)d_in[6];
    const float* ln2_w    = (const float*)d_in[7];
    const float* ln2_b    = (const float*)d_in[8];
    const float* fc_w     = (const float*)d_in[9];
    const float* fc_b     = (const float*)d_in[10];
    const float* proj_w   = (const float*)d_in[11];
    const float* proj_b   = (const float*)d_in[12];
    float* out = (float*)d_out;

    float *ln1, *qkv, *attn, *x1, *ln2o, *hbuf;
    cudaGetSymbolAddress((void**)&ln1,  g_ln1);
    cudaGetSymbolAddress((void**)&qkv,  g_qkv);
    cudaGetSymbolAddress((void**)&attn, g_attn);
    cudaGetSymbolAddress((void**)&x1,   g_x1);
    cudaGetSymbolAddress((void**)&ln2o, g_ln2);
    cudaGetSymbolAddress((void**)&hbuf, g_h);

    static bool attr_done = false;
    if (!attr_done) {
        cudaFuncSetAttribute(gemm_tc<0>, cudaFuncAttributeMaxDynamicSharedMemorySize, GEMM_SMEM_BYTES);
        cudaFuncSetAttribute(gemm_tc<1>, cudaFuncAttributeMaxDynamicSharedMemorySize, GEMM_SMEM_BYTES);
        cudaFuncSetAttribute(gemm_tc<2>, cudaFuncAttributeMaxDynamicSharedMemorySize, GEMM_SMEM_BYTES);
        cudaFuncSetAttribute(attn_tc,    cudaFuncAttributeMaxDynamicSharedMemorySize, ATTN_SMEM);
        attr_done = true;
    }

    ln_kernel<<<NTOK, 256>>>(x, ln1_w, ln1_b, ln1);
    gemm_tc<0><<<dim3(3 * D_MODEL / BN, NTOK / BM), 256, GEMM_SMEM_BYTES>>>(
        ln1, c_attn_w, c_attn_b, nullptr, qkv, NTOK, 3 * D_MODEL, D_MODEL);
    attn_tc<<<dim3(SEQ / QT, NHEAD, BATCH), 256, ATTN_SMEM>>>(qkv, attn);
    gemm_tc<1><<<dim3(D_MODEL / BN, NTOK / BM), 256, GEMM_SMEM_BYTES>>>(
        attn, c_proj_w, c_proj_b, x, x1, NTOK, D_MODEL, D_MODEL);
    ln_kernel<<<NTOK, 256>>>(x1, ln2_w, ln2_b, ln2o);
    gemm_tc<2><<<dim3(4 * D_MODEL / BN, NTOK / BM), 256, GEMM_SMEM_BYTES>>>(
        ln2o, fc_w, fc_b, nullptr, hbuf, NTOK, 4 * D_MODEL, D_MODEL);
    gemm_tc<1><<<dim3(D_MODEL / BN, NTOK / BM), 256, GEMM_SMEM_BYTES>>>(
        hbuf, proj_w, proj_b, x1, out, NTOK, D_MODEL, 4 * D_MODEL);
}

// round 6
// speedup vs baseline: 5.4377x; 1.4212x over previous
#include <cuda_runtime.h>
#include <cuda_fp16.h>
#include <math.h>
#include <stdint.h>

#define D_MODEL 1024
#define SEQ     2048
#define BATCH   2
#define NTOK    4096
#define NHEAD   16
#define HD      64

// ---------------- scratch ----------------
__device__ float  g_qkv [NTOK * 3 * D_MODEL];
__device__ float  g_x1  [NTOK * D_MODEL];
__device__ __half g_ln1h[NTOK * D_MODEL];
__device__ __half g_attnh[NTOK * D_MODEL];
__device__ __half g_ln2h[NTOK * D_MODEL];
__device__ __half g_hh  [NTOK * 4 * D_MODEL];
// fp16 weights, k-pair interleaved: w16[((k>>1)*N + n)*2 + (k&1)]
__device__ __half g_wattn [D_MODEL * 3 * D_MODEL];
__device__ __half g_wproj [D_MODEL * D_MODEL];
__device__ __half g_wfc   [D_MODEL * 4 * D_MODEL];
__device__ __half g_wproj2[4 * D_MODEL * D_MODEL];

// raw fp32 bits as tf32 operand
__device__ __forceinline__ uint32_t f2tf(float x) { return __float_as_uint(x); }
__device__ __forceinline__ float rntf(float x)
{
    uint32_t r;
    asm("cvt.rna.tf32.f32 %0, %1;\n" : "=r"(r) : "f"(x));
    return __uint_as_float(r);
}

// ---------------- weight fp32 -> fp16 interleaved ----------------
__global__ __launch_bounds__(256) void wconv(const float* __restrict__ w,
                                             __half* __restrict__ o,
                                             int K, int N)
{
    int idx = blockIdx.x * 256 + threadIdx.x;   // over (K/2)*N
    if (idx >= (K / 2) * N) return;
    int kp = idx / N, n = idx - kp * N;
    float lo = w[(size_t)(2 * kp) * N + n];
    float hi = w[(size_t)(2 * kp + 1) * N + n];
    ((__half2*)o)[idx] = __floats2half2_rn(lo, hi);
}

// ---------------- LayerNorm -> fp16 ----------------
__global__ __launch_bounds__(256) void ln_kernel(const float* __restrict__ x,
                                                 const float* __restrict__ w,
                                                 const float* __restrict__ b,
                                                 __half* __restrict__ y)
{
    int row = blockIdx.x;
    int tid = threadIdx.x;
    const float4* xr = (const float4*)(x + (size_t)row * D_MODEL);
    float4 v = xr[tid];

    __shared__ float red[8];

    float s = v.x + v.y + v.z + v.w;
    #pragma unroll
    for (int o = 16; o > 0; o >>= 1) s += __shfl_xor_sync(0xffffffffu, s, o);
    if ((tid & 31) == 0) red[tid >> 5] = s;
    __syncthreads();
    float tot = red[0] + red[1] + red[2] + red[3] + red[4] + red[5] + red[6] + red[7];
    float mean = tot * (1.0f / 1024.0f);

    float a0 = v.x - mean, a1 = v.y - mean, a2 = v.z - mean, a3 = v.w - mean;
    __syncthreads();
    float q = a0*a0 + a1*a1 + a2*a2 + a3*a3;
    #pragma unroll
    for (int o = 16; o > 0; o >>= 1) q += __shfl_xor_sync(0xffffffffu, q, o);
    if ((tid & 31) == 0) red[tid >> 5] = q;
    __syncthreads();
    float ssq = red[0] + red[1] + red[2] + red[3] + red[4] + red[5] + red[6] + red[7];

    float sd  = sqrtf(ssq * (1.0f / 1023.0f));
    float inv = 1.0f / (sd + 1e-5f);

    float4 wv = ((const float4*)w)[tid];
    float4 bv = ((const float4*)b)[tid];
    __half2* yr = (__half2*)(y + (size_t)row * D_MODEL);
    yr[2 * tid]     = __floats2half2_rn(wv.x * (a0 * inv) + bv.x,
                                        wv.y * (a1 * inv) + bv.y);
    yr[2 * tid + 1] = __floats2half2_rn(wv.z * (a2 * inv) + bv.z,
                                        wv.w * (a3 * inv) + bv.w);
}

__device__ __forceinline__ float gelu_f(float x)
{
    float x3 = x * x * x;
    return 0.5f * x * (1.0f + tanhf(0.7978845608028654f * (x + 0.044715f * x3)));
}

__device__ __forceinline__ void cp16(uint32_t dst, const void* src)
{
    asm volatile("cp.async.cg.shared.global [%0], [%1], 16;\n" :: "r"(dst), "l"(src));
}

#define MMA_F16(c, a, b) \
    asm volatile( \
        "mma.sync.aligned.m16n8k16.row.col.f32.f16.f16.f32 " \
        "{%0,%1,%2,%3}, {%4,%5,%6,%7}, {%8,%9}, {%0,%1,%2,%3};\n" \
        : "+f"((c)[0]), "+f"((c)[1]), "+f"((c)[2]), "+f"((c)[3]) \
        : "r"((a)[0]), "r"((a)[1]), "r"((a)[2]), "r"((a)[3]), \
          "r"((b)[0]), "r"((b)[1]))

#define MMA_TF32(c, a, b) \
    asm volatile( \
        "mma.sync.aligned.m16n8k8.row.col.f32.tf32.tf32.f32 " \
        "{%0,%1,%2,%3}, {%4,%5,%6,%7}, {%8,%9}, {%0,%1,%2,%3};\n" \
        : "+f"((c)[0]), "+f"((c)[1]), "+f"((c)[2]), "+f"((c)[3]) \
        : "r"((a)[0]), "r"((a)[1]), "r"((a)[2]), "r"((a)[3]), \
          "r"((b)[0]), "r"((b)[1]))

// ---------------- fp16 GEMM 128x128x32, 3-stage cp.async ----------------
// A: fp16 [M,K] row-major. B: fp16 interleaved [K/2][N][2]. C: fp32 or fp16.
#define BM 128
#define BN 128
#define BKT 32
#define A_ROW_H 40                         // halfs per A smem row (80B)
#define A_STAGE_BYTES (BM * A_ROW_H * 2)   // 10240
#define B_ROW_W 136                        // words per kpair row (544B)
#define B_STAGE_BYTES (16 * B_ROW_W * 4)   // 8704
#define STAGE_BYTES (A_STAGE_BYTES + B_STAGE_BYTES)   // 18944
#define GEMM_SMEM_BYTES (3 * STAGE_BYTES)  // 56832

// MODE 0: qkv = A@B + bias (fp32, tf32-rounded)
// MODE 1: C = res + A@B + bias (fp32)
// MODE 2: Ch = gelu(A@B + bias) (fp16)
template<int MODE>
__global__ __launch_bounds__(256, 2) void gemm_fp16(const __half* __restrict__ A,
                                                    const __half* __restrict__ Bw16,
                                                    const float* __restrict__ bias,
                                                    const float* __restrict__ res,
                                                    float* __restrict__ C,
                                                    __half* __restrict__ Ch,
                                                    int M, int N, int K)
{
    extern __shared__ char smc[];
    int tid  = threadIdx.x;
    int bx = blockIdx.x, by = blockIdx.y;
    int warp = tid >> 5, lane = tid & 31;
    int wm = warp >> 2, wn = warp & 3;          // 2x4 warps, 64x32 warp tile
    int g = lane >> 2, tig = lane & 3;

    const __half* Ablk = A + (size_t)(by * BM) * K;
    const __half* Bblk = Bw16 + (size_t)(bx * BN) * 2;   // n offset in interleaved layout

    float c[4][4][4];
    #pragma unroll
    for (int mt = 0; mt < 4; mt++)
        #pragma unroll
        for (int nt = 0; nt < 4; nt++)
            #pragma unroll
            for (int r = 0; r < 4; r++) c[mt][nt][r] = 0.0f;

    const int iters = K / BKT;
    uint32_t smem_base = (uint32_t)__cvta_generic_to_shared(smc);

    auto load_stage = [&](int it, int buf) {
        uint32_t as = smem_base + (uint32_t)(buf * STAGE_BYTES);
        uint32_t bs = as + A_STAGE_BYTES;
        int k0 = it * BKT;
        // A: 128 rows x 32 halfs = 512 x 16B chunks
        #pragma unroll
        for (int i = 0; i < 2; i++) {
            int q = tid + 256 * i;
            int ar = q >> 2, ac = (q & 3) * 8;          // halfs
            cp16(as + (uint32_t)(ar * (A_ROW_H * 2) + ac * 2),
                 Ablk + (size_t)ar * K + k0 + ac);
            // B: 16 kpair rows x 128 words = 512 x 16B chunks
            int br = q >> 5, bc = (q & 31) * 4;         // words
            cp16(bs + (uint32_t)(br * (B_ROW_W * 4) + bc * 4),
                 Bblk + ((size_t)(k0 / 2 + br) * N + bc) * 2);
        }
        asm volatile("cp.async.commit_group;\n" ::: "memory");
    };

    load_stage(0, 0);
    if (iters > 1) load_stage(1, 1);

    for (int it = 0; it < iters; it++) {
        if (it + 1 < iters) asm volatile("cp.async.wait_group 1;\n" ::: "memory");
        else                asm volatile("cp.async.wait_group 0;\n" ::: "memory");
        __syncthreads();                       // all warps done with it-1
        if (it + 2 < iters) {
            int nb = (it + 2) % 3;
            load_stage(it + 2, nb);
        }

        const char* stg = smc + (it % 3) * STAGE_BYTES;
        const __half*  As = (const __half*)stg;
        const uint32_t* Bs = (const uint32_t*)(stg + A_STAGE_BYTES);

        #pragma unroll
        for (int s = 0; s < 2; s++) {          // two k16 steps
            uint32_t a[4][4], b[4][2];
            #pragma unroll
            for (int mt = 0; mt < 4; mt++) {
                int m = wm * 64 + mt * 16 + g;
                const __half* ar0 = As + m * A_ROW_H + s * 16 + 2 * tig;
                const __half* ar1 = ar0 + 8 * A_ROW_H;
                a[mt][0] = *(const uint32_t*)ar0;
                a[mt][1] = *(const uint32_t*)ar1;
                a[mt][2] = *(const uint32_t*)(ar0 + 8);
                a[mt][3] = *(const uint32_t*)(ar1 + 8);
            }
            #pragma unroll
            for (int nt = 0; nt < 4; nt++) {
                int n = wn * 32 + nt * 8 + g;
                b[nt][0] = Bs[(s * 8 + tig) * B_ROW_W + n];
                b[nt][1] = Bs[(s * 8 + 4 + tig) * B_ROW_W + n];
            }
            #pragma unroll
            for (int mt = 0; mt < 4; mt++)
                #pragma unroll
                for (int nt = 0; nt < 4; nt++)
                    MMA_F16(c[mt][nt], a[mt], b[nt]);
        }
    }

    #pragma unroll
    for (int mt = 0; mt < 4; mt++) {
        int row0 = by * BM + wm * 64 + mt * 16 + g;
        #pragma unroll
        for (int nt = 0; nt < 4; nt++) {
            int col = bx * BN + wn * 32 + nt * 8 + tig * 2;
            float b0 = __ldg(bias + col), b1 = __ldg(bias + col + 1);
            float v0 = c[mt][nt][0] + b0, v1 = c[mt][nt][1] + b1;
            float v2 = c[mt][nt][2] + b0, v3 = c[mt][nt][3] + b1;
            if (MODE == 0) {
                *(float2*)(C + (size_t)row0 * N + col) =
                    make_float2(rntf(v0), rntf(v1));
                *(float2*)(C + (size_t)(row0 + 8) * N + col) =
                    make_float2(rntf(v2), rntf(v3));
            }
            if (MODE == 1) {
                const float* r0 = res + (size_t)row0 * N + col;
                const float* r1 = res + (size_t)(row0 + 8) * N + col;
                *(float2*)(C + (size_t)row0 * N + col) =
                    make_float2(v0 + r0[0], v1 + r0[1]);
                *(float2*)(C + (size_t)(row0 + 8) * N + col) =
                    make_float2(v2 + r1[0], v3 + r1[1]);
            }
            if (MODE == 2) {
                *(__half2*)(Ch + (size_t)row0 * N + col) =
                    __floats2half2_rn(gelu_f(v0), gelu_f(v1));
                *(__half2*)(Ch + (size_t)(row0 + 8) * N + col) =
                    __floats2half2_rn(gelu_f(v2), gelu_f(v3));
            }
        }
    }
}

// ---------------- tensor-core flash attention (tf32, fp16 output) ----------------
#define QT 128
#define KT 64
#define QS_STR 68
#define KS_STR 68
#define VS_STR 72
#define PS_STR 68
#define ATTN_SMEM ((QT*QS_STR + KT*KS_STR + KT*VS_STR + QT*PS_STR) * 4)

__global__ __launch_bounds__(256, 2) void attn_tc(const float* __restrict__ qkv,
                                                  __half* __restrict__ out)
{
    extern __shared__ float sm[];
    float* Qs = sm;
    float* Ks = Qs + QT * QS_STR;
    float* Vs = Ks + KT * KS_STR;
    float* Ps = Vs + KT * VS_STR;

    int tid = threadIdx.x, warp = tid >> 5, lane = tid & 31;
    int g = lane >> 2, tig = lane & 3;
    int qb = gridDim.x - 1 - blockIdx.x;
    int h = blockIdx.y, b = blockIdx.z;

    const float* base = qkv + (size_t)b * SEQ * (3 * D_MODEL) + h * HD;

    uint32_t qs_u = (uint32_t)__cvta_generic_to_shared(Qs);
    uint32_t ks_u = (uint32_t)__cvta_generic_to_shared(Ks);
    uint32_t vs_u = (uint32_t)__cvta_generic_to_shared(Vs);

    #pragma unroll
    for (int i = 0; i < 8; i++) {
        int idx = i * 256 + tid;
        int r = idx >> 4, d4 = (idx & 15) * 4;
        cp16(qs_u + (uint32_t)(r * QS_STR + d4) * 4u,
             base + (size_t)(qb * QT + r) * (3 * D_MODEL) + d4);
    }
    asm volatile("cp.async.commit_group;\n" ::: "memory");

    float o[8][4];
    #pragma unroll
    for (int nt = 0; nt < 8; nt++)
        #pragma unroll
        for (int r = 0; r < 4; r++) o[nt][r] = 0.0f;
    float m0 = -INFINITY, m1 = -INFINITY, l0 = 0.0f, l1 = 0.0f;

    int qrow_lo = qb * QT + warp * 16;
    int kb_end = 2 * qb + 1;

    for (int kb = 0; kb <= kb_end; kb++) {
        __syncthreads();
        #pragma unroll
        for (int i = 0; i < 4; i++) {
            int idx = i * 256 + tid;
            int r = idx >> 4, d4 = (idx & 15) * 4;
            const float* krow = base + D_MODEL + (size_t)(kb * KT + r) * (3 * D_MODEL) + d4;
            cp16(ks_u + (uint32_t)(r * KS_STR + d4) * 4u, krow);
            cp16(vs_u + (uint32_t)(r * VS_STR + d4) * 4u, krow + D_MODEL);
        }
        asm volatile("cp.async.commit_group;\n" ::: "memory");
        asm volatile("cp.async.wait_group 0;\n" ::: "memory");
        __syncthreads();

        if (kb * 64 > qrow_lo + 15) continue;

        float s[8][4];
        #pragma unroll
        for (int nt = 0; nt < 8; nt++)
            #pragma unroll
            for (int r = 0; r < 4; r++) s[nt][r] = 0.0f;

        #pragma unroll
        for (int ks = 0; ks < 8; ks++) {
            int kbq = ks * 8;
            uint32_t a[4], bb[8][2];
            int mrow = warp * 16 + g;
            a[0] = f2tf(Qs[mrow * QS_STR + kbq + tig]);
            a[1] = f2tf(Qs[(mrow + 8) * QS_STR + kbq + tig]);
            a[2] = f2tf(Qs[mrow * QS_STR + kbq + tig + 4]);
            a[3] = f2tf(Qs[(mrow + 8) * QS_STR + kbq + tig + 4]);
            #pragma unroll
            for (int nt = 0; nt < 8; nt++) {
                bb[nt][0] = f2tf(Ks[(nt * 8 + g) * KS_STR + kbq + tig]);
                bb[nt][1] = f2tf(Ks[(nt * 8 + g) * KS_STR + kbq + tig + 4]);
            }
            #pragma unroll
            for (int nt = 0; nt < 8; nt++) MMA_TF32(s[nt], a, bb[nt]);
        }

        const float scale = 0.125f;
        int q0 = qb * QT + warp * 16 + g;
        int q1 = q0 + 8;
        bool diag = (kb * 64 + 63 > qrow_lo);
        #pragma unroll
        for (int nt = 0; nt < 8; nt++) {
            int key = kb * 64 + nt * 8 + 2 * tig;
            s[nt][0] *= scale; s[nt][1] *= scale;
            s[nt][2] *= scale; s[nt][3] *= scale;
            if (diag) {
                if (key     > q0) s[nt][0] = -1e30f;
                if (key + 1 > q0) s[nt][1] = -1e30f;
                if (key     > q1) s[nt][2] = -1e30f;
                if (key + 1 > q1) s[nt][3] = -1e30f;
            }
        }

        float rmax0 = -INFINITY, rmax1 = -INFINITY;
        #pragma unroll
        for (int nt = 0; nt < 8; nt++) {
            rmax0 = fmaxf(rmax0, fmaxf(s[nt][0], s[nt][1]));
            rmax1 = fmaxf(rmax1, fmaxf(s[nt][2], s[nt][3]));
        }
        rmax0 = fmaxf(rmax0, __shfl_xor_sync(0xffffffffu, rmax0, 1));
        rmax0 = fmaxf(rmax0, __shfl_xor_sync(0xffffffffu, rmax0, 2));
        rmax1 = fmaxf(rmax1, __shfl_xor_sync(0xffffffffu, rmax1, 1));
        rmax1 = fmaxf(rmax1, __shfl_xor_sync(0xffffffffu, rmax1, 2));

        float mn0 = fmaxf(m0, rmax0), mn1 = fmaxf(m1, rmax1);
        float corr0 = __expf(m0 - mn0), corr1 = __expf(m1 - mn1);

        float rs0 = 0.0f, rs1 = 0.0f;
        #pragma unroll
        for (int nt = 0; nt < 8; nt++) {
            s[nt][0] = __expf(s[nt][0] - mn0);
            s[nt][1] = __expf(s[nt][1] - mn0);
            s[nt][2] = __expf(s[nt][2] - mn1);
            s[nt][3] = __expf(s[nt][3] - mn1);
            rs0 += s[nt][0] + s[nt][1];
            rs1 += s[nt][2] + s[nt][3];
        }
        rs0 += __shfl_xor_sync(0xffffffffu, rs0, 1);
        rs0 += __shfl_xor_sync(0xffffffffu, rs0, 2);
        rs1 += __shfl_xor_sync(0xffffffffu, rs1, 1);
        rs1 += __shfl_xor_sync(0xffffffffu, rs1, 2);

        l0 = l0 * corr0 + rs0;  m0 = mn0;
        l1 = l1 * corr1 + rs1;  m1 = mn1;

        int pr0 = warp * 16 + g;
        #pragma unroll
        for (int nt = 0; nt < 8; nt++) {
            *(float2*)&Ps[pr0 * PS_STR + nt * 8 + 2 * tig]       = make_float2(s[nt][0], s[nt][1]);
            *(float2*)&Ps[(pr0 + 8) * PS_STR + nt * 8 + 2 * tig] = make_float2(s[nt][2], s[nt][3]);
        }
        __syncwarp();

        #pragma unroll
        for (int nt = 0; nt < 8; nt++) {
            o[nt][0] *= corr0; o[nt][1] *= corr0;
            o[nt][2] *= corr1; o[nt][3] *= corr1;
        }

        #pragma unroll
        for (int ks = 0; ks < 8; ks++) {
            int kbq = ks * 8;
            uint32_t a[4], bb[8][2];
            a[0] = f2tf(Ps[pr0 * PS_STR + kbq + tig]);
            a[1] = f2tf(Ps[(pr0 + 8) * PS_STR + kbq + tig]);
            a[2] = f2tf(Ps[pr0 * PS_STR + kbq + tig + 4]);
            a[3] = f2tf(Ps[(pr0 + 8) * PS_STR + kbq + tig + 4]);
            #pragma unroll
            for (int nt = 0; nt < 8; nt++) {
                bb[nt][0] = f2tf(Vs[(kbq + tig) * VS_STR + nt * 8 + g]);
                bb[nt][1] = f2tf(Vs[(kbq + tig + 4) * VS_STR + nt * 8 + g]);
            }
            #pragma unroll
            for (int nt = 0; nt < 8; nt++) MMA_TF32(o[nt], a, bb[nt]);
        }
    }

    float il0 = 1.0f / l0, il1 = 1.0f / l1;
    size_t row0 = (size_t)(b * SEQ + qb * QT + warp * 16 + g);
    #pragma unroll
    for (int nt = 0; nt < 8; nt++) {
        int col = h * HD + nt * 8 + 2 * tig;
        *(__half2*)(out + row0 * D_MODEL + col) =
            __floats2half2_rn(o[nt][0] * il0, o[nt][1] * il0);
        *(__half2*)(out + (row0 + 8) * D_MODEL + col) =
            __floats2half2_rn(o[nt][2] * il1, o[nt][3] * il1);
    }
}

// ---------------- launch ----------------
extern "C" void kernel_launch(void* const* d_in, const int* in_sizes, int n_in,
                              void* d_out, int out_size)
{
    const float* x        = (const float*)d_in[0];
    const float* ln1_w    = (const float*)d_in[1];
    const float* ln1_b    = (const float*)d_in[2];
    const float* c_attn_w = (const float*)d_in[3];
    const float* c_attn_b = (const float*)d_in[4];
    const float* c_proj_w = (const float*)d_in[5];
    const float* c_proj_b = (const float*)d_in[6];
    const float* ln2_w    = (const float*)d_in[7];
    const float* ln2_b    = (const float*)d_in[8];
    const float* fc_w     = (const float*)d_in[9];
    const float* fc_b     = (const float*)d_in[10];
    const float* proj_w   = (const float*)d_in[11];
    const float* proj_b   = (const float*)d_in[12];
    float* out = (float*)d_out;

    float  *qkv, *x1;
    __half *ln1h, *attnh, *ln2h, *hh, *wattn, *wproj, *wfc, *wproj2;
    cudaGetSymbolAddress((void**)&qkv,   g_qkv);
    cudaGetSymbolAddress((void**)&x1,    g_x1);
    cudaGetSymbolAddress((void**)&ln1h,  g_ln1h);
    cudaGetSymbolAddress((void**)&attnh, g_attnh);
    cudaGetSymbolAddress((void**)&ln2h,  g_ln2h);
    cudaGetSymbolAddress((void**)&hh,    g_hh);
    cudaGetSymbolAddress((void**)&wattn, g_wattn);
    cudaGetSymbolAddress((void**)&wproj, g_wproj);
    cudaGetSymbolAddress((void**)&wfc,   g_wfc);
    cudaGetSymbolAddress((void**)&wproj2, g_wproj2);

    static bool attr_done = false;
    if (!attr_done) {
        cudaFuncSetAttribute(gemm_fp16<0>, cudaFuncAttributeMaxDynamicSharedMemorySize, GEMM_SMEM_BYTES);
        cudaFuncSetAttribute(gemm_fp16<1>, cudaFuncAttributeMaxDynamicSharedMemorySize, GEMM_SMEM_BYTES);
        cudaFuncSetAttribute(gemm_fp16<2>, cudaFuncAttributeMaxDynamicSharedMemorySize, GEMM_SMEM_BYTES);
        cudaFuncSetAttribute(attn_tc,      cudaFuncAttributeMaxDynamicSharedMemorySize, ATTN_SMEM);
        attr_done = true;
    }

    // weight conversions (per replay; ~15us total)
    wconv<<<(D_MODEL / 2 * 3 * D_MODEL + 255) / 256, 256>>>(c_attn_w, wattn, D_MODEL, 3 * D_MODEL);
    wconv<<<(D_MODEL / 2 * D_MODEL + 255) / 256, 256>>>(c_proj_w, wproj, D_MODEL, D_MODEL);
    wconv<<<(D_MODEL / 2 * 4 * D_MODEL + 255) / 256, 256>>>(fc_w, wfc, D_MODEL, 4 * D_MODEL);
    wconv<<<(4 * D_MODEL / 2 * D_MODEL + 255) / 256, 256>>>(proj_w, wproj2, 4 * D_MODEL, D_MODEL);

    ln_kernel<<<NTOK, 256>>>(x, ln1_w, ln1_b, ln1h);
    gemm_fp16<0><<<dim3(3 * D_MODEL / BN, NTOK / BM), 256, GEMM_SMEM_BYTES>>>(
        ln1h, wattn, c_attn_b, nullptr, qkv, nullptr, NTOK, 3 * D_MODEL, D_MODEL);
    attn_tc<<<dim3(SEQ / QT, NHEAD, BATCH), 256, ATTN_SMEM>>>(qkv, attnh);
    gemm_fp16<1><<<dim3(D_MODEL / BN, NTOK / BM), 256, GEMM_SMEM_BYTES>>>(
        attnh, wproj, c_proj_b, x, x1, nullptr, NTOK, D_MODEL, D_MODEL);
    ln_kernel<<<NTOK, 256>>>(x1, ln2_w, ln2_b, ln2h);
    gemm_fp16<2><<<dim3(4 * D_MODEL / BN, NTOK / BM), 256, GEMM_SMEM_BYTES>>>(
        ln2h, wfc, fc_b, nullptr, nullptr, hh, NTOK, 4 * D_MODEL, D_MODEL);
    gemm_fp16<1><<<dim3(D_MODEL / BN, NTOK / BM), 256, GEMM_SMEM_BYTES>>>(
        hh, wproj2, proj_b, x1, out, nullptr, NTOK, D_MODEL, 4 * D_MODEL);
}

// round 8
// speedup vs baseline: 5.5892x; 1.0279x over previous
#include <cuda_runtime.h>
#include <cuda_fp16.h>
#include <math.h>
#include <stdint.h>

#define D_MODEL 1024
#define SEQ     2048
#define BATCH   2
#define NTOK    4096
#define NHEAD   16
#define HD      64

// ---------------- scratch ----------------
__device__ float  g_x1  [NTOK * D_MODEL];
__device__ __half g_qkv [NTOK * 3 * D_MODEL];
__device__ __half g_ln1h[NTOK * D_MODEL];
__device__ __half g_attnh[NTOK * D_MODEL];
__device__ __half g_ln2h[NTOK * D_MODEL];
__device__ __half g_hh  [NTOK * 4 * D_MODEL];
// fp16 weights, k-pair interleaved: w16[((k>>1)*N + n)*2 + (k&1)]
__device__ __half g_wattn [D_MODEL * 3 * D_MODEL];
__device__ __half g_wproj [D_MODEL * D_MODEL];
__device__ __half g_wfc   [D_MODEL * 4 * D_MODEL];
__device__ __half g_wproj2[4 * D_MODEL * D_MODEL];

// ---------------- weight fp32 -> fp16 interleaved (vectorized) ----------------
__global__ __launch_bounds__(256) void wconv(const float* __restrict__ w,
                                             __half* __restrict__ o,
                                             int K, int N)
{
    int idx = blockIdx.x * 256 + threadIdx.x;   // over (K/2)*(N/4)
    int nq4 = N >> 2;
    if (idx >= (K / 2) * nq4) return;
    int kp = idx / nq4, n = (idx - kp * nq4) * 4;
    float4 lo = *(const float4*)(w + (size_t)(2 * kp) * N + n);
    float4 hi = *(const float4*)(w + (size_t)(2 * kp + 1) * N + n);
    __half2 h0 = __floats2half2_rn(lo.x, hi.x);
    __half2 h1 = __floats2half2_rn(lo.y, hi.y);
    __half2 h2 = __floats2half2_rn(lo.z, hi.z);
    __half2 h3 = __floats2half2_rn(lo.w, hi.w);
    uint4 pack;
    pack.x = *(uint32_t*)&h0; pack.y = *(uint32_t*)&h1;
    pack.z = *(uint32_t*)&h2; pack.w = *(uint32_t*)&h3;
    *(uint4*)(o + ((size_t)kp * N + n) * 2) = pack;
}

// ---------------- LayerNorm -> fp16 ----------------
__global__ __launch_bounds__(256) void ln_kernel(const float* __restrict__ x,
                                                 const float* __restrict__ w,
                                                 const float* __restrict__ b,
                                                 __half* __restrict__ y)
{
    int row = blockIdx.x;
    int tid = threadIdx.x;
    const float4* xr = (const float4*)(x + (size_t)row * D_MODEL);
    float4 v = xr[tid];

    __shared__ float red[8];

    float s = v.x + v.y + v.z + v.w;
    #pragma unroll
    for (int o = 16; o > 0; o >>= 1) s += __shfl_xor_sync(0xffffffffu, s, o);
    if ((tid & 31) == 0) red[tid >> 5] = s;
    __syncthreads();
    float tot = red[0] + red[1] + red[2] + red[3] + red[4] + red[5] + red[6] + red[7];
    float mean = tot * (1.0f / 1024.0f);

    float a0 = v.x - mean, a1 = v.y - mean, a2 = v.z - mean, a3 = v.w - mean;
    __syncthreads();
    float q = a0*a0 + a1*a1 + a2*a2 + a3*a3;
    #pragma unroll
    for (int o = 16; o > 0; o >>= 1) q += __shfl_xor_sync(0xffffffffu, q, o);
    if ((tid & 31) == 0) red[tid >> 5] = q;
    __syncthreads();
    float ssq = red[0] + red[1] + red[2] + red[3] + red[4] + red[5] + red[6] + red[7];

    float sd  = sqrtf(ssq * (1.0f / 1023.0f));
    float inv = 1.0f / (sd + 1e-5f);

    float4 wv = ((const float4*)w)[tid];
    float4 bv = ((const float4*)b)[tid];
    __half2* yr = (__half2*)(y + (size_t)row * D_MODEL);
    yr[2 * tid]     = __floats2half2_rn(wv.x * (a0 * inv) + bv.x,
                                        wv.y * (a1 * inv) + bv.y);
    yr[2 * tid + 1] = __floats2half2_rn(wv.z * (a2 * inv) + bv.z,
                                        wv.w * (a3 * inv) + bv.w);
}

__device__ __forceinline__ float gelu_f(float x)
{
    float x3 = x * x * x;
    return 0.5f * x * (1.0f + tanhf(0.7978845608028654f * (x + 0.044715f * x3)));
}

__device__ __forceinline__ void cp16(uint32_t dst, const void* src)
{
    asm volatile("cp.async.cg.shared.global [%0], [%1], 16;\n" :: "r"(dst), "l"(src));
}

#define MMA_F16(c, a, b) \
    asm volatile( \
        "mma.sync.aligned.m16n8k16.row.col.f32.f16.f16.f32 " \
        "{%0,%1,%2,%3}, {%4,%5,%6,%7}, {%8,%9}, {%0,%1,%2,%3};\n" \
        : "+f"((c)[0]), "+f"((c)[1]), "+f"((c)[2]), "+f"((c)[3]) \
        : "r"((a)[0]), "r"((a)[1]), "r"((a)[2]), "r"((a)[3]), \
          "r"((b)[0]), "r"((b)[1]))

#define LDSM_X4(r0, r1, r2, r3, addr) \
    asm volatile("ldmatrix.sync.aligned.m8n8.x4.shared.b16 {%0,%1,%2,%3}, [%4];" \
        : "=r"(r0), "=r"(r1), "=r"(r2), "=r"(r3) : "r"(addr))

// ---------------- fp16 GEMM 128x128x32, 3-stage cp.async ----------------
#define BM 128
#define BN 128
#define BKT 32
#define A_ROW_H 40
#define A_STAGE_BYTES (BM * A_ROW_H * 2)
#define B_ROW_W 136
#define B_STAGE_BYTES (16 * B_ROW_W * 4)
#define STAGE_BYTES (A_STAGE_BYTES + B_STAGE_BYTES)
#define GEMM_SMEM_BYTES (3 * STAGE_BYTES)

// MODE 0: qkv(half) = A@B + bias ; MODE 1: C = res + A@B + bias (fp32)
// MODE 2: Ch = gelu(A@B + bias) (fp16)
template<int MODE>
__global__ __launch_bounds__(256, 2) void gemm_fp16(const __half* __restrict__ A,
                                                    const __half* __restrict__ Bw16,
                                                    const float* __restrict__ bias,
                                                    const float* __restrict__ res,
                                                    float* __restrict__ C,
                                                    __half* __restrict__ Ch,
                                                    int M, int N, int K)
{
    extern __shared__ char smc[];
    int tid  = threadIdx.x;
    int bx = blockIdx.x, by = blockIdx.y;
    int warp = tid >> 5, lane = tid & 31;
    int wm = warp >> 2, wn = warp & 3;
    int g = lane >> 2, tig = lane & 3;

    // ldmatrix address components
    int lr8  = lane & 7;
    int aoff = ((lane & 8) ? 8 : 0);          // +8 rows
    int koff = ((lane & 16) ? 8 : 0);         // +8 k

    const __half* Ablk = A + (size_t)(by * BM) * K;
    const __half* Bblk = Bw16 + (size_t)(bx * BN) * 2;

    float c[4][4][4];
    #pragma unroll
    for (int mt = 0; mt < 4; mt++)
        #pragma unroll
        for (int nt = 0; nt < 4; nt++)
            #pragma unroll
            for (int r = 0; r < 4; r++) c[mt][nt][r] = 0.0f;

    const int iters = K / BKT;
    uint32_t smem_base = (uint32_t)__cvta_generic_to_shared(smc);

    auto load_stage = [&](int it, int buf) {
        uint32_t as = smem_base + (uint32_t)(buf * STAGE_BYTES);
        uint32_t bs = as + A_STAGE_BYTES;
        int k0 = it * BKT;
        #pragma unroll
        for (int i = 0; i < 2; i++) {
            int q = tid + 256 * i;
            int ar = q >> 2, ac = (q & 3) * 8;
            cp16(as + (uint32_t)(ar * (A_ROW_H * 2) + ac * 2),
                 Ablk + (size_t)ar * K + k0 + ac);
            int br = q >> 5, bc = (q & 31) * 4;
            cp16(bs + (uint32_t)(br * (B_ROW_W * 4) + bc * 4),
                 Bblk + ((size_t)(k0 / 2 + br) * N + bc) * 2);
        }
        asm volatile("cp.async.commit_group;\n" ::: "memory");
    };

    load_stage(0, 0);
    if (iters > 1) load_stage(1, 1);

    for (int it = 0; it < iters; it++) {
        if (it + 1 < iters) asm volatile("cp.async.wait_group 1;\n" ::: "memory");
        else                asm volatile("cp.async.wait_group 0;\n" ::: "memory");
        __syncthreads();
        if (it + 2 < iters) load_stage(it + 2, (it + 2) % 3);

        const char* stg = smc + (it % 3) * STAGE_BYTES;
        const __half*  As = (const __half*)stg;
        const uint32_t* Bs = (const uint32_t*)(stg + A_STAGE_BYTES);

        #pragma unroll
        for (int s = 0; s < 2; s++) {
            uint32_t a[4][4], b[4][2];
            #pragma unroll
            for (int mt = 0; mt < 4; mt++) {
                const __half* p = As + (size_t)(wm * 64 + mt * 16 + lr8 + aoff) * A_ROW_H
                                     + s * 16 + koff;
                uint32_t ad = (uint32_t)__cvta_generic_to_shared(p);
                LDSM_X4(a[mt][0], a[mt][1], a[mt][2], a[mt][3], ad);
            }
            #pragma unroll
            for (int nt = 0; nt < 4; nt++) {
                int n = wn * 32 + nt * 8 + g;
                b[nt][0] = Bs[(s * 8 + tig) * B_ROW_W + n];
                b[nt][1] = Bs[(s * 8 + 4 + tig) * B_ROW_W + n];
            }
            #pragma unroll
            for (int mt = 0; mt < 4; mt++)
                #pragma unroll
                for (int nt = 0; nt < 4; nt++)
                    MMA_F16(c[mt][nt], a[mt], b[nt]);
        }
    }

    #pragma unroll
    for (int mt = 0; mt < 4; mt++) {
        int row0 = by * BM + wm * 64 + mt * 16 + g;
        #pragma unroll
        for (int nt = 0; nt < 4; nt++) {
            int col = bx * BN + wn * 32 + nt * 8 + tig * 2;
            float b0 = __ldg(bias + col), b1 = __ldg(bias + col + 1);
            float v0 = c[mt][nt][0] + b0, v1 = c[mt][nt][1] + b1;
            float v2 = c[mt][nt][2] + b0, v3 = c[mt][nt][3] + b1;
            if (MODE == 0) {
                *(__half2*)(Ch + (size_t)row0 * N + col) = __floats2half2_rn(v0, v1);
                *(__half2*)(Ch + (size_t)(row0 + 8) * N + col) = __floats2half2_rn(v2, v3);
            }
            if (MODE == 1) {
                const float* r0 = res + (size_t)row0 * N + col;
                const float* r1 = res + (size_t)(row0 + 8) * N + col;
                *(float2*)(C + (size_t)row0 * N + col) =
                    make_float2(v0 + r0[0], v1 + r0[1]);
                *(float2*)(C + (size_t)(row0 + 8) * N + col) =
                    make_float2(v2 + r1[0], v3 + r1[1]);
            }
            if (MODE == 2) {
                *(__half2*)(Ch + (size_t)row0 * N + col) =
                    __floats2half2_rn(gelu_f(v0), gelu_f(v1));
                *(__half2*)(Ch + (size_t)(row0 + 8) * N + col) =
                    __floats2half2_rn(gelu_f(v2), gelu_f(v3));
            }
        }
    }
}

// ---------------- fp16 tensor-core flash attention ----------------
// qkv fp16 [token][3*D]. Q/K/P tiles row-major, V transposed to [d][key].
// All strides 72 halfs (36 words, %32==4 -> conflict-free frag LDS).
#define QT 128
#define KT 64
#define TS_H 72
#define ATTN_SMEM ((QT*TS_H + KT*TS_H + KT*TS_H + QT*TS_H) * 2)

__global__ __launch_bounds__(256, 2) void attn_tc(const __half* __restrict__ qkv,
                                                  __half* __restrict__ out)
{
    extern __shared__ __half smh[];
    __half* Qs = smh;                       // [128][72]
    __half* Ks = Qs + QT * TS_H;            // [64][72]
    __half* Vt = Ks + KT * TS_H;            // [64 d][72 keys]
    __half* Ps = Vt + KT * TS_H;            // [128][72]

    int tid = threadIdx.x, warp = tid >> 5, lane = tid & 31;
    int g = lane >> 2, tig = lane & 3;
    int qb = gridDim.x - 1 - blockIdx.x;
    int h = blockIdx.y, b = blockIdx.z;

    const __half* base = qkv + (size_t)b * SEQ * (3 * D_MODEL) + h * HD;

    uint32_t qs_u = (uint32_t)__cvta_generic_to_shared(Qs);
    uint32_t ks_u = (uint32_t)__cvta_generic_to_shared(Ks);
    uint32_t* Vtw = (uint32_t*)Vt;
    const uint32_t* Qsw = (const uint32_t*)Qs;
    const uint32_t* Ksw = (const uint32_t*)Ks;
    const uint32_t* Vw  = (const uint32_t*)Vt;
    uint32_t* Psw = (uint32_t*)Ps;

    // Q tile 128 x 64 halfs = 1024 x 16B
    #pragma unroll
    for (int i = 0; i < 4; i++) {
        int idx = i * 256 + tid;
        int r = idx >> 3, c8 = (idx & 7) * 8;
        cp16(qs_u + (uint32_t)(r * TS_H + c8) * 2u,
             base + (size_t)(qb * QT + r) * (3 * D_MODEL) + c8);
    }
    asm volatile("cp.async.commit_group;\n" ::: "memory");

    float o[8][4];
    #pragma unroll
    for (int nt = 0; nt < 8; nt++)
        #pragma unroll
        for (int r = 0; r < 4; r++) o[nt][r] = 0.0f;
    float m0 = -INFINITY, m1 = -INFINITY, l0 = 0.0f, l1 = 0.0f;

    int qrow_lo = qb * QT + warp * 16;
    int kb_end = 2 * qb + 1;

    // V transpose mapping
    int tp = tid & 31;          // token pair
    int dgrp = tid >> 5;        // 8 d per group

    for (int kb = 0; kb <= kb_end; kb++) {
        __syncthreads();
        // K tile 64x64 halfs = 512 x 16B via cp.async
        #pragma unroll
        for (int i = 0; i < 2; i++) {
            int idx = i * 256 + tid;
            int r = idx >> 3, c8 = (idx & 7) * 8;
            cp16(ks_u + (uint32_t)(r * TS_H + c8) * 2u,
                 base + D_MODEL + (size_t)(kb * KT + r) * (3 * D_MODEL) + c8);
        }
        asm volatile("cp.async.commit_group;\n" ::: "memory");

        // V transpose: LDG half2 pairs, repack, STS.32 into Vt[d][key]
        {
            const __half* v0r = base + 2 * D_MODEL + (size_t)(kb * KT + 2 * tp) * (3 * D_MODEL);
            const __half* v1r = v0r + 3 * D_MODEL;
            #pragma unroll
            for (int j = 0; j < 4; j++) {
                int d = dgrp * 8 + 2 * j;
                __half2 a = *(const __half2*)(v0r + d);
                __half2 bb = *(const __half2*)(v1r + d);
                __half2 lo = __lows2half2(a, bb);    // (V[t][d], V[t+1][d])
                __half2 hi = __highs2half2(a, bb);
                Vtw[d * 36 + tp]       = *(uint32_t*)&lo;
                Vtw[(d + 1) * 36 + tp] = *(uint32_t*)&hi;
            }
        }
        asm volatile("cp.async.wait_group 0;\n" ::: "memory");
        __syncthreads();

        if (kb * 64 > qrow_lo + 15) continue;

        // ---- S = Q K^T (fp16 MMA, 4 k16 steps) ----
        float s[8][4];
        #pragma unroll
        for (int nt = 0; nt < 8; nt++)
            #pragma unroll
            for (int r = 0; r < 4; r++) s[nt][r] = 0.0f;

        int mrow = warp * 16 + g;
        #pragma unroll
        for (int ks = 0; ks < 4; ks++) {
            uint32_t a[4], bb[8][2];
            a[0] = Qsw[mrow * 36 + ks * 8 + tig];
            a[1] = Qsw[(mrow + 8) * 36 + ks * 8 + tig];
            a[2] = Qsw[mrow * 36 + ks * 8 + 4 + tig];
            a[3] = Qsw[(mrow + 8) * 36 + ks * 8 + 4 + tig];
            #pragma unroll
            for (int nt = 0; nt < 8; nt++) {
                bb[nt][0] = Ksw[(nt * 8 + g) * 36 + ks * 8 + tig];
                bb[nt][1] = Ksw[(nt * 8 + g) * 36 + ks * 8 + 4 + tig];
            }
            #pragma unroll
            for (int nt = 0; nt < 8; nt++) MMA_F16(s[nt], a, bb[nt]);
        }

        const float scale = 0.125f;
        int q0 = qb * QT + warp * 16 + g;
        int q1 = q0 + 8;
        bool diag = (kb * 64 + 63 > qrow_lo);
        #pragma unroll
        for (int nt = 0; nt < 8; nt++) {
            int key = kb * 64 + nt * 8 + 2 * tig;
            s[nt][0] *= scale; s[nt][1] *= scale;
            s[nt][2] *= scale; s[nt][3] *= scale;
            if (diag) {
                if (key     > q0) s[nt][0] = -1e30f;
                if (key + 1 > q0) s[nt][1] = -1e30f;
                if (key     > q1) s[nt][2] = -1e30f;
                if (key + 1 > q1) s[nt][3] = -1e30f;
            }
        }

        float rmax0 = -INFINITY, rmax1 = -INFINITY;
        #pragma unroll
        for (int nt = 0; nt < 8; nt++) {
            rmax0 = fmaxf(rmax0, fmaxf(s[nt][0], s[nt][1]));
            rmax1 = fmaxf(rmax1, fmaxf(s[nt][2], s[nt][3]));
        }
        rmax0 = fmaxf(rmax0, __shfl_xor_sync(0xffffffffu, rmax0, 1));
        rmax0 = fmaxf(rmax0, __shfl_xor_sync(0xffffffffu, rmax0, 2));
        rmax1 = fmaxf(rmax1, __shfl_xor_sync(0xffffffffu, rmax1, 1));
        rmax1 = fmaxf(rmax1, __shfl_xor_sync(0xffffffffu, rmax1, 2));

        float mn0 = fmaxf(m0, rmax0), mn1 = fmaxf(m1, rmax1);
        float corr0 = __expf(m0 - mn0), corr1 = __expf(m1 - mn1);

        float rs0 = 0.0f, rs1 = 0.0f;
        #pragma unroll
        for (int nt = 0; nt < 8; nt++) {
            s[nt][0] = __expf(s[nt][0] - mn0);
            s[nt][1] = __expf(s[nt][1] - mn0);
            s[nt][2] = __expf(s[nt][2] - mn1);
            s[nt][3] = __expf(s[nt][3] - mn1);
            rs0 += s[nt][0] + s[nt][1];
            rs1 += s[nt][2] + s[nt][3];
        }
        rs0 += __shfl_xor_sync(0xffffffffu, rs0, 1);
        rs0 += __shfl_xor_sync(0xffffffffu, rs0, 2);
        rs1 += __shfl_xor_sync(0xffffffffu, rs1, 1);
        rs1 += __shfl_xor_sync(0xffffffffu, rs1, 2);

        l0 = l0 * corr0 + rs0;  m0 = mn0;
        l1 = l1 * corr1 + rs1;  m1 = mn1;

        // ---- P (fp16) to warp-private smem ----
        int pr0 = warp * 16 + g;
        #pragma unroll
        for (int nt = 0; nt < 8; nt++) {
            __half2 p0 = __floats2half2_rn(s[nt][0], s[nt][1]);
            __half2 p1 = __floats2half2_rn(s[nt][2], s[nt][3]);
            Psw[pr0 * 36 + nt * 4 + tig]       = *(uint32_t*)&p0;
            Psw[(pr0 + 8) * 36 + nt * 4 + tig] = *(uint32_t*)&p1;
        }
        __syncwarp();

        #pragma unroll
        for (int nt = 0; nt < 8; nt++) {
            o[nt][0] *= corr0; o[nt][1] *= corr0;
            o[nt][2] *= corr1; o[nt][3] *= corr1;
        }

        // ---- O += P V (fp16 MMA; B from Vt[d][key]) ----
        #pragma unroll
        for (int ks = 0; ks < 4; ks++) {
            uint32_t a[4], bb[8][2];
            a[0] = Psw[pr0 * 36 + ks * 8 + tig];
            a[1] = Psw[(pr0 + 8) * 36 + ks * 8 + tig];
            a[2] = Psw[pr0 * 36 + ks * 8 + 4 + tig];
            a[3] = Psw[(pr0 + 8) * 36 + ks * 8 + 4 + tig];
            #pragma unroll
            for (int nt = 0; nt < 8; nt++) {
                bb[nt][0] = Vw[(nt * 8 + g) * 36 + ks * 8 + tig];
                bb[nt][1] = Vw[(nt * 8 + g) * 36 + ks * 8 + 4 + tig];
            }
            #pragma unroll
            for (int nt = 0; nt < 8; nt++) MMA_F16(o[nt], a, bb[nt]);
        }
    }

    float il0 = 1.0f / l0, il1 = 1.0f / l1;
    size_t row0 = (size_t)(b * SEQ + qb * QT + warp * 16 + g);
    #pragma unroll
    for (int nt = 0; nt < 8; nt++) {
        int col = h * HD + nt * 8 + 2 * tig;
        *(__half2*)(out + row0 * D_MODEL + col) =
            __floats2half2_rn(o[nt][0] * il0, o[nt][1] * il0);
        *(__half2*)(out + (row0 + 8) * D_MODEL + col) =
            __floats2half2_rn(o[nt][2] * il1, o[nt][3] * il1);
    }
}

// ---------------- launch ----------------
extern "C" void kernel_launch(void* const* d_in, const int* in_sizes, int n_in,
                              void* d_out, int out_size)
{
    const float* x        = (const float*)d_in[0];
    const float* ln1_w    = (const float*)d_in[1];
    const float* ln1_b    = (const float*)d_in[2];
    const float* c_attn_w = (const float*)d_in[3];
    const float* c_attn_b = (const float*)d_in[4];
    const float* c_proj_w = (const float*)d_in[5];
    const float* c_proj_b = (const float*)d_in[6];
    const float* ln2_w    = (const float*)d_in[7];
    const float* ln2_b    = (const float*)d_in[8];
    const float* fc_w     = (const float*)d_in[9];
    const float* fc_b     = (const float*)d_in[10];
    const float* proj_w   = (const float*)d_in[11];
    const float* proj_b   = (const float*)d_in[12];
    float* out = (float*)d_out;

    float  *x1;
    __half *qkv, *ln1h, *attnh, *ln2h, *hh, *wattn, *wproj, *wfc, *wproj2;
    cudaGetSymbolAddress((void**)&x1,    g_x1);
    cudaGetSymbolAddress((void**)&qkv,   g_qkv);
    cudaGetSymbolAddress((void**)&ln1h,  g_ln1h);
    cudaGetSymbolAddress((void**)&attnh, g_attnh);
    cudaGetSymbolAddress((void**)&ln2h,  g_ln2h);
    cudaGetSymbolAddress((void**)&hh,    g_hh);
    cudaGetSymbolAddress((void**)&wattn, g_wattn);
    cudaGetSymbolAddress((void**)&wproj, g_wproj);
    cudaGetSymbolAddress((void**)&wfc,   g_wfc);
    cudaGetSymbolAddress((void**)&wproj2, g_wproj2);

    static bool attr_done = false;
    if (!attr_done) {
        cudaFuncSetAttribute(gemm_fp16<0>, cudaFuncAttributeMaxDynamicSharedMemorySize, GEMM_SMEM_BYTES);
        cudaFuncSetAttribute(gemm_fp16<1>, cudaFuncAttributeMaxDynamicSharedMemorySize, GEMM_SMEM_BYTES);
        cudaFuncSetAttribute(gemm_fp16<2>, cudaFuncAttributeMaxDynamicSharedMemorySize, GEMM_SMEM_BYTES);
        cudaFuncSetAttribute(attn_tc,      cudaFuncAttributeMaxDynamicSharedMemorySize, ATTN_SMEM);
        attr_done = true;
    }

    wconv<<<(D_MODEL / 2 * 3 * D_MODEL / 4 + 255) / 256, 256>>>(c_attn_w, wattn, D_MODEL, 3 * D_MODEL);
    wconv<<<(D_MODEL / 2 * D_MODEL / 4 + 255) / 256, 256>>>(c_proj_w, wproj, D_MODEL, D_MODEL);
    wconv<<<(D_MODEL / 2 * 4 * D_MODEL / 4 + 255) / 256, 256>>>(fc_w, wfc, D_MODEL, 4 * D_MODEL);
    wconv<<<(4 * D_MODEL / 2 * D_MODEL / 4 + 255) / 256, 256>>>(proj_w, wproj2, 4 * D_MODEL, D_MODEL);

    ln_kernel<<<NTOK, 256>>>(x, ln1_w, ln1_b, ln1h);
    gemm_fp16<0><<<dim3(3 * D_MODEL / BN, NTOK / BM), 256, GEMM_SMEM_BYTES>>>(
        ln1h, wattn, c_attn_b, nullptr, nullptr, qkv, NTOK, 3 * D_MODEL, D_MODEL);
    attn_tc<<<dim3(SEQ / QT, NHEAD, BATCH), 256, ATTN_SMEM>>>(qkv, attnh);
    gemm_fp16<1><<<dim3(D_MODEL / BN, NTOK / BM), 256, GEMM_SMEM_BYTES>>>(
        attnh, wproj, c_proj_b, x, x1, nullptr, NTOK, D_MODEL, D_MODEL);
    ln_kernel<<<NTOK, 256>>>(x1, ln2_w, ln2_b, ln2h);
    gemm_fp16<2><<<dim3(4 * D_MODEL / BN, NTOK / BM), 256, GEMM_SMEM_BYTES>>>(
        ln2h, wfc, fc_b, nullptr, nullptr, hh, NTOK, 4 * D_MODEL, D_MODEL);
    gemm_fp16<1><<<dim3(D_MODEL / BN, NTOK / BM), 256, GEMM_SMEM_BYTES>>>(
        hh, wproj2, proj_b, x1, out, nullptr, NTOK, D_MODEL, 4 * D_MODEL);
}